// round 13
// baseline (speedup 1.0000x reference)
#include <cuda_runtime.h>
#include <cuda_fp16.h>
#include <cstddef>
#include <cstdint>
#include <math.h>

// ---------------- problem constants ----------------
#define T_  2048
#define H_  4096
#define HQ_ 32
#define HKV_ 8
#define D_  128
#define I_  14336

// ---------------- scratch (device globals; no allocation allowed) ----------------
__device__ __half g_h   [T_ * H_];            // rmsnorm out (fp16)
__device__ __half g_qh  [T_ * HQ_ * D_];      // q fp16 (pre+post rope, in place)
__device__ __half g_kh  [T_ * HKV_ * D_];     // k fp16 (pre+post rope, in place)
__device__ __half g_vh  [T_ * HKV_ * D_];     // v fp16
__device__ __half g_attn[T_ * H_];            // attention out (fp16)
__device__ float  g_x1  [T_ * H_];
__device__ __half g_gate[T_ * (size_t)I_];
__device__ __half g_gu  [T_ * (size_t)I_];
// fp16 weight copies (qkv concatenated: wq 4096 rows | wk 1024 | wv 1024)
__device__ __half g_wqkv[(size_t)(H_ + 2 * HKV_ * D_) * H_];
__device__ __half g_wo[(size_t)H_ * H_];
__device__ __half g_wg[(size_t)I_ * H_];
__device__ __half g_wu[(size_t)I_ * H_];
__device__ __half g_wd[(size_t)H_ * I_];

// ---------------- helpers ----------------
__device__ __forceinline__ uint32_t smem_u32(const void* p) {
    return (uint32_t)__cvta_generic_to_shared(p);
}
__device__ __forceinline__ void cp_async16(uint32_t saddr, const void* gmem) {
    asm volatile("cp.async.cg.shared.global [%0], [%1], 16;\n" :: "r"(saddr), "l"(gmem));
}
#define CP_COMMIT() asm volatile("cp.async.commit_group;\n" ::: "memory")

__device__ __forceinline__ void ldsm4(uint32_t& r0, uint32_t& r1, uint32_t& r2,
                                      uint32_t& r3, uint32_t addr) {
    asm volatile("ldmatrix.sync.aligned.m8n8.x4.shared.b16 {%0,%1,%2,%3}, [%4];"
                 : "=r"(r0), "=r"(r1), "=r"(r2), "=r"(r3) : "r"(addr));
}
__device__ __forceinline__ void ldsm4t(uint32_t& r0, uint32_t& r1, uint32_t& r2,
                                       uint32_t& r3, uint32_t addr) {
    asm volatile("ldmatrix.sync.aligned.m8n8.x4.trans.shared.b16 {%0,%1,%2,%3}, [%4];"
                 : "=r"(r0), "=r"(r1), "=r"(r2), "=r"(r3) : "r"(addr));
}
__device__ __forceinline__ void mma_f16(float* c,
    uint32_t a0, uint32_t a1, uint32_t a2, uint32_t a3, uint32_t b0, uint32_t b1)
{
    asm volatile(
        "mma.sync.aligned.m16n8k16.row.col.f32.f16.f16.f32 "
        "{%0,%1,%2,%3}, {%4,%5,%6,%7}, {%8,%9}, {%0,%1,%2,%3};"
        : "+f"(c[0]), "+f"(c[1]), "+f"(c[2]), "+f"(c[3])
        : "r"(a0), "r"(a1), "r"(a2), "r"(a3), "r"(b0), "r"(b1));
}
__device__ __forceinline__ uint32_t packh2(float a, float b) {
    __half2 h = __floats2half2_rn(a, b);
    return *(uint32_t*)&h;
}

// ---------------- fused weight convert fp32 -> fp16 (ONE launch, big-first) ----------------
#define S_WQ 4194304L
#define S_WK 1048576L
#define S_WV 1048576L
#define S_WO 4194304L
#define S_WG 14680064L
#define S_WU 14680064L
#define S_WD 14680064L
#define S_TOTAL (S_WQ + S_WK + S_WV + S_WO + S_WG + S_WU + S_WD)

__global__ void __launch_bounds__(256) f2h_all_kernel(
    const float4* __restrict__ wq, const float4* __restrict__ wk,
    const float4* __restrict__ wv, const float4* __restrict__ wo,
    const float4* __restrict__ wg, const float4* __restrict__ wu,
    const float4* __restrict__ wd,
    __half2* __restrict__ dqkv, __half2* __restrict__ dwo,
    __half2* __restrict__ dwg, __half2* __restrict__ dwu,
    __half2* __restrict__ dwd)
{
    long i = (long)blockIdx.x * 256 + threadIdx.x;
    if (i >= S_TOTAL) return;
    const float4* src;
    __half2* dst;
    long j = i;
    // big tensors first: 81% of indices resolve in <=3 compares
    if (j < S_WG)                      { src = wg; dst = dwg; }
    else if ((j -= S_WG) < S_WU)       { src = wu; dst = dwu; }
    else if ((j -= S_WU) < S_WD)       { src = wd; dst = dwd; }
    else if ((j -= S_WD) < S_WQ)       { src = wq; dst = dqkv; }
    else if ((j -= S_WQ) < S_WO)       { src = wo; dst = dwo; }
    else if ((j -= S_WO) < S_WK)       { src = wk; dst = dqkv + 2 * S_WQ; }
    else                { j -= S_WK;     src = wv; dst = dqkv + 2 * (S_WQ + S_WK); }
    float4 v = src[j];
    dst[2 * j]     = __floats2half2_rn(v.x, v.y);
    dst[2 * j + 1] = __floats2half2_rn(v.z, v.w);
}

// ---------------- RMSNorm (fp16 output) ----------------
__global__ void __launch_bounds__(256) rmsnorm_kernel(
    const float* __restrict__ x, const float* __restrict__ w, __half* __restrict__ out)
{
    const int row = blockIdx.x;
    const float4* xv = (const float4*)(x + (size_t)row * H_);
    const float4* wv = (const float4*)w;
    __half2* ov = (__half2*)(out + (size_t)row * H_);

    float4 buf[4];
    float ss = 0.f;
#pragma unroll
    for (int i = 0; i < 4; i++) {
        float4 v = xv[threadIdx.x + i * 256];
        buf[i] = v;
        ss += v.x * v.x + v.y * v.y + v.z * v.z + v.w * v.w;
    }
#pragma unroll
    for (int o = 16; o; o >>= 1) ss += __shfl_xor_sync(0xffffffffu, ss, o);

    __shared__ float wsum[8];
    __shared__ float s_inv;
    if ((threadIdx.x & 31) == 0) wsum[threadIdx.x >> 5] = ss;
    __syncthreads();
    if (threadIdx.x == 0) {
        float tot = 0.f;
#pragma unroll
        for (int i = 0; i < 8; i++) tot += wsum[i];
        s_inv = rsqrtf(tot * (1.f / (float)H_) + 1e-5f);
    }
    __syncthreads();
    const float inv = s_inv;
#pragma unroll
    for (int i = 0; i < 4; i++) {
        float4 v = buf[i];
        float4 ww = wv[threadIdx.x + i * 256];
        ov[(threadIdx.x + i * 256) * 2]     = __floats2half2_rn(v.x * inv * ww.x, v.y * inv * ww.y);
        ov[(threadIdx.x + i * 256) * 2 + 1] = __floats2half2_rn(v.z * inv * ww.z, v.w * inv * ww.w);
    }
}

// ---------------- fused RoPE (q + k), IN-PLACE on fp16, 4 heads/block ----------------
__global__ void __launch_bounds__(256) rope2_kernel(
    __half* __restrict__ qo, __half* __restrict__ ko, const int* __restrict__ pos)
{
    const int tt = blockIdx.x;
    int h = blockIdx.y * 4 + (threadIdx.x >> 6);   // 0..39
    const int j = threadIdx.x & 63;
    const float p = (float)pos[tt];
    const float invf = expf(-(float)j * 0.20503692777194262f);
    float s, c;
    sincosf(p * invf, &s, &c);
    __half* ob;
    if (h < HQ_) {
        ob = qo + ((size_t)tt * HQ_ + h) * D_ + j;
    } else {
        h -= HQ_;
        ob = ko + ((size_t)tt * HKV_ + h) * D_ + j;
    }
    const float x1v = __half2float(ob[0]);
    const float x2v = __half2float(ob[64]);
    ob[0]  = __float2half(x1v * c - x2v * s);
    ob[64] = __float2half(x2v * c + x1v * s);
}

// ---------------- fp16 tensor-core GEMM: C[M,N] = A[M,K] * B[N,K]^T ----------------
// ROUND-9 CONFIG (empirical optimum): 256 thr, 8 warps 2x4, warp 64x32,
// 3-stage cp.async, single barrier per k-tile, 2 CTAs/SM, grid = (N/128, M/128).
// MODE 0: store  1: C=Cin(f32)+acc  2: C=silu(acc)  3: C=Cin(f16)*acc  4: QKV split (all fp16)
// OUTH: 1 -> fp16 output, 0 -> fp32 output
#define STAGE_A 16384
#define STAGE_BYTES 32768
#define GEMM_SMEM (3 * STAGE_BYTES)

template <int MODE, int OUTH>
__global__ void __launch_bounds__(256, 2) gemm_f16_kernel(
    const __half* __restrict__ A, const __half* __restrict__ B,
    const void* __restrict__ Cin, void* __restrict__ Cv,
    void* __restrict__ Cv2, void* __restrict__ Cv3, int N, int K)
{
    extern __shared__ __align__(1024) char smem[];
    const uint32_t sbase = smem_u32(smem);
    const int tid  = threadIdx.x;
    const int wid  = tid >> 5;
    const int lane = tid & 31;
    const int warpM = (wid >> 2) * 64;
    const int warpN = (wid & 3) * 32;
    const size_t arow0 = (size_t)blockIdx.y * 128;
    const size_t brow0 = (size_t)blockIdx.x * 128;
    const int ntiles = K >> 6;

    const int lrow = tid >> 1;
    const int lch  = (tid & 1) * 4;
    const __half* Ag = A + (arow0 + lrow) * K + lch * 8;
    const __half* Bg = B + (brow0 + lrow) * K + lch * 8;
    uint32_t s_off[4];
#pragma unroll
    for (int i = 0; i < 4; i++) {
        uint32_t o = (uint32_t)(lrow * 128 + (lch + i) * 16);
        s_off[i] = o ^ ((o >> 3) & 0x70);
    }

#define LOADT(t, slot)                                                   \
    {                                                                    \
        const uint32_t sa = sbase + (slot) * STAGE_BYTES;                \
        const __half* ag = Ag + (size_t)(t) * 64;                        \
        const __half* bg = Bg + (size_t)(t) * 64;                        \
        _Pragma("unroll")                                                \
        for (int i = 0; i < 4; i++) {                                    \
            cp_async16(sa + s_off[i], ag + i * 8);                       \
            cp_async16(sa + STAGE_A + s_off[i], bg + i * 8);             \
        }                                                                \
    }

    uint32_t aRow[4], aMask[4], bRow[2], bMask[2];
    const int kbA = (lane >> 4) * 16;
    {
        const int r = lane & 15;
#pragma unroll
        for (int mi = 0; mi < 4; mi++) {
            uint32_t o = (uint32_t)((warpM + mi * 16 + r) * 128);
            aRow[mi]  = o;
            aMask[mi] = (o >> 3) & 0x70;
        }
    }
    const int rn  = (lane & 7) + ((lane >> 4) << 3);
    const int kbB = ((lane >> 3) & 1) * 16;
    {
#pragma unroll
        for (int ni = 0; ni < 2; ni++) {
            uint32_t o = (uint32_t)((warpN + ni * 16 + rn) * 128);
            bRow[ni]  = o;
            bMask[ni] = (o >> 3) & 0x70;
        }
    }

    float acc[4][4][4];
#pragma unroll
    for (int mi = 0; mi < 4; mi++)
#pragma unroll
        for (int nj = 0; nj < 4; nj++)
#pragma unroll
            for (int r = 0; r < 4; r++) acc[mi][nj][r] = 0.f;

    LOADT(0, 0); CP_COMMIT();
    LOADT(1, 1); CP_COMMIT();

    for (int t = 0; t < ntiles; t++) {
        asm volatile("cp.async.wait_group 1;\n" ::: "memory");
        __syncthreads();
        if (t + 2 < ntiles) { LOADT(t + 2, (t + 2) % 3); }
        CP_COMMIT();

        const uint32_t sa = sbase + (t % 3) * STAGE_BYTES;
#pragma unroll
        for (int ks = 0; ks < 4; ks++) {
            uint32_t b[2][4];
#pragma unroll
            for (int ni = 0; ni < 2; ni++)
                ldsm4(b[ni][0], b[ni][1], b[ni][2], b[ni][3],
                      sa + STAGE_A + bRow[ni] + (((uint32_t)(kbB + ks * 32)) ^ bMask[ni]));
#pragma unroll
            for (int mi = 0; mi < 4; mi++) {
                uint32_t a0, a1, a2, a3;
                ldsm4(a0, a1, a2, a3,
                      sa + aRow[mi] + (((uint32_t)(kbA + ks * 32)) ^ aMask[mi]));
#pragma unroll
                for (int nj = 0; nj < 4; nj++)
                    mma_f16(acc[mi][nj], a0, a1, a2, a3,
                            b[nj >> 1][(nj & 1) * 2], b[nj >> 1][(nj & 1) * 2 + 1]);
            }
        }
    }
#undef LOADT

    // epilogue
    const int r0 = (int)arow0 + warpM + (lane >> 2);
    if (MODE == 4) {
        // QKV concat: cols [0,4096)->q fp16 ; [4096,5120)->k fp16 ; [5120,6144)->v fp16
        const int gcol0 = blockIdx.x * 128 + warpN + (lane & 3) * 2;
        __half* outH;
        int Nout, col0;
        if (gcol0 < 4096)      { outH = (__half*)Cv;  Nout = H_;         col0 = gcol0; }
        else if (gcol0 < 5120) { outH = (__half*)Cv2; Nout = HKV_ * D_;  col0 = gcol0 - 4096; }
        else                   { outH = (__half*)Cv3; Nout = HKV_ * D_;  col0 = gcol0 - 5120; }
#pragma unroll
        for (int mi = 0; mi < 4; mi++) {
#pragma unroll
            for (int h = 0; h < 2; h++) {
                const int row = r0 + mi * 16 + h * 8;
#pragma unroll
                for (int nj = 0; nj < 4; nj++) {
                    const int col = col0 + nj * 8;
                    *(__half2*)(outH + (size_t)row * Nout + col) =
                        __floats2half2_rn(acc[mi][nj][h * 2 + 0], acc[mi][nj][h * 2 + 1]);
                }
            }
        }
        return;
    }

    const int c0 = blockIdx.x * 128 + warpN + (lane & 3) * 2;
#pragma unroll
    for (int mi = 0; mi < 4; mi++) {
#pragma unroll
        for (int h = 0; h < 2; h++) {
            const int row = r0 + mi * 16 + h * 8;
#pragma unroll
            for (int nj = 0; nj < 4; nj++) {
                const int col = c0 + nj * 8;
                float vx = acc[mi][nj][h * 2 + 0];
                float vy = acc[mi][nj][h * 2 + 1];
                if (MODE == 1) {
                    const float* cin = (const float*)Cin + (size_t)row * N + col;
                    vx += cin[0];
                    vy += cin[1];
                } else if (MODE == 2) {
                    vx = vx / (1.f + expf(-vx));
                    vy = vy / (1.f + expf(-vy));
                } else if (MODE == 3) {
                    const __half2 c2 = *(const __half2*)((const __half*)Cin + (size_t)row * N + col);
                    const float2 cf = __half22float2(c2);
                    vx *= cf.x;
                    vy *= cf.y;
                }
                if (OUTH) {
                    __half2* dst = (__half2*)((__half*)Cv + (size_t)row * N + col);
                    *dst = __floats2half2_rn(vx, vy);
                } else {
                    float2* dst = (float2*)((float*)Cv + (size_t)row * N + col);
                    *dst = make_float2(vx, vy);
                }
            }
        }
    }
}

// ---------------- fp16 tensor-core causal flash attention ----------------
// grid (8, HQ): CTA bx processes q-blocks {bx, 15-bx} -> uniform 32 KV-tiles per CTA.
#define AQ_OFF   0
#define AKV_OFF  32768
#define AKV_STRIDE 32768
#define ATT_SMEM (32768 + 2 * AKV_STRIDE)   // 96KB

__global__ void __launch_bounds__(256) attn16_kernel(
    const __half* __restrict__ qh, const __half* __restrict__ kh,
    const __half* __restrict__ vh, __half* __restrict__ o)
{
    extern __shared__ __align__(1024) char smem[];
    const uint32_t sbase = smem_u32(smem);
    const int tid  = threadIdx.x;
    const int wid  = tid >> 5;
    const int lane = tid & 31;
    const int bx   = blockIdx.x;        // 0..7
    const int head = blockIdx.y;
    const int kvh  = head >> 2;
    const float scale = 0.08838834764831845f;

    const int rA    = lane & 15;
    const int kbA   = (lane >> 4) * 16;
    const int rnB   = (lane & 7) + ((lane >> 4) << 3);
    const int kbB   = ((lane >> 3) & 1) * 16;
    const int rV    = (lane & 7) + ((lane >> 3) & 1) * 8;
    const int dbV   = ((lane >> 4) & 1) * 16;

#define LOADKV(kt, buf)                                                              \
    {                                                                                \
        const int k0l = (kt) * 64;                                                   \
        const uint32_t kb = sbase + AKV_OFF + (buf) * AKV_STRIDE;                    \
        _Pragma("unroll")                                                            \
        for (int i = 0; i < 4; i++) {                                                \
            const int chunk = tid + 256 * i;                                         \
            const int seg = chunk >> 9;                                              \
            const int row = (chunk >> 3) & 63;                                       \
            const int off = chunk & 7;                                               \
            const uint32_t ro = (uint32_t)(row * 128);                               \
            const uint32_t sw = ro + (((uint32_t)(off * 16)) ^ ((ro >> 3) & 0x70));  \
            const size_t gi = (size_t)(k0l + row) * (HKV_ * D_) + kvh * D_           \
                            + seg * 64 + off * 8;                                    \
            cp_async16(kb + seg * 8192 + sw, kh + gi);                               \
            cp_async16(kb + 16384 + seg * 8192 + sw, vh + gi);                       \
        }                                                                            \
    }

#pragma unroll 1
    for (int it = 0; it < 2; it++) {
        const int qblk = (it == 0) ? bx : (15 - bx);
        const int q0   = qblk * 128;
        const int qr0  = q0 + wid * 16;

        // ---- load Q tile ----
#pragma unroll
        for (int i = 0; i < 8; i++) {
            const int chunk = tid + 256 * i;
            const int seg = chunk >> 10;
            const int row = (chunk >> 3) & 127;
            const int off = chunk & 7;
            const uint32_t ro = (uint32_t)(row * 128);
            const uint32_t sw = ro + (((uint32_t)(off * 16)) ^ ((ro >> 3) & 0x70));
            cp_async16(sbase + AQ_OFF + seg * 16384 + sw,
                       qh + (size_t)(q0 + row) * (HQ_ * D_) + head * D_ + seg * 64 + off * 8);
        }
        CP_COMMIT();
        LOADKV(0, 0); CP_COMMIT();

        uint32_t qf[8][4];
        float accO[16][4];
#pragma unroll
        for (int nj = 0; nj < 16; nj++)
#pragma unroll
            for (int r = 0; r < 4; r++) accO[nj][r] = 0.f;
        float m1 = -1e30f, m2 = -1e30f, l1 = 0.f, l2 = 0.f;

        const int ktmax = 2 * qblk + 1;
        for (int kt = 0; kt <= ktmax; kt++) {
            if (kt < ktmax) {
                LOADKV(kt + 1, (kt + 1) & 1);
                CP_COMMIT();
                asm volatile("cp.async.wait_group 1;\n" ::: "memory");
            } else {
                asm volatile("cp.async.wait_group 0;\n" ::: "memory");
            }
            __syncthreads();

            if (kt == 0) {
#pragma unroll
                for (int ks = 0; ks < 8; ks++) {
                    const int seg = ks >> 2;
                    const uint32_t ro = (uint32_t)((wid * 16 + rA) * 128);
                    const uint32_t addr = sbase + AQ_OFF + seg * 16384 + ro
                        + (((uint32_t)(kbA + (ks & 3) * 32)) ^ ((ro >> 3) & 0x70));
                    ldsm4(qf[ks][0], qf[ks][1], qf[ks][2], qf[ks][3], addr);
                }
            }

            const int k0 = kt * 64;
            if (k0 <= qr0 + 15) {
                const uint32_t kbuf = sbase + AKV_OFF + (kt & 1) * AKV_STRIDE;
                float s[8][4];
#pragma unroll
                for (int nj = 0; nj < 8; nj++)
#pragma unroll
                    for (int r = 0; r < 4; r++) s[nj][r] = 0.f;

#pragma unroll
                for (int ks = 0; ks < 8; ks++) {
                    const int seg = ks >> 2;
                    uint32_t b[4][4];
#pragma unroll
                    for (int ni = 0; ni < 4; ni++) {
                        const uint32_t ro = (uint32_t)((ni * 16 + rnB) * 128);
                        ldsm4(b[ni][0], b[ni][1], b[ni][2], b[ni][3],
                              kbuf + seg * 8192 + ro
                              + (((uint32_t)(kbB + (ks & 3) * 32)) ^ ((ro >> 3) & 0x70)));
                    }
#pragma unroll
                    for (int nj = 0; nj < 8; nj++)
                        mma_f16(s[nj], qf[ks][0], qf[ks][1], qf[ks][2], qf[ks][3],
                                b[nj >> 1][(nj & 1) * 2], b[nj >> 1][(nj & 1) * 2 + 1]);
                }

                const int row1 = qr0 + (lane >> 2);
                const int row2 = row1 + 8;
                float rmax1 = -1e30f, rmax2 = -1e30f;
#pragma unroll
                for (int nj = 0; nj < 8; nj++) {
                    const int c0 = k0 + nj * 8 + (lane & 3) * 2;
                    float v0 = s[nj][0] * scale, v1 = s[nj][1] * scale;
                    float v2 = s[nj][2] * scale, v3 = s[nj][3] * scale;
                    if (c0 > row1)     v0 = -1e30f;
                    if (c0 + 1 > row1) v1 = -1e30f;
                    if (c0 > row2)     v2 = -1e30f;
                    if (c0 + 1 > row2) v3 = -1e30f;
                    s[nj][0] = v0; s[nj][1] = v1; s[nj][2] = v2; s[nj][3] = v3;
                    rmax1 = fmaxf(rmax1, fmaxf(v0, v1));
                    rmax2 = fmaxf(rmax2, fmaxf(v2, v3));
                }
#pragma unroll
                for (int off = 1; off <= 2; off <<= 1) {
                    rmax1 = fmaxf(rmax1, __shfl_xor_sync(0xffffffffu, rmax1, off));
                    rmax2 = fmaxf(rmax2, __shfl_xor_sync(0xffffffffu, rmax2, off));
                }
                const float mn1 = fmaxf(m1, rmax1);
                const float mn2 = fmaxf(m2, rmax2);
                const float al1 = expf(m1 - mn1);
                const float al2 = expf(m2 - mn2);
                m1 = mn1; m2 = mn2;

                float ps1 = 0.f, ps2 = 0.f;
#pragma unroll
                for (int nj = 0; nj < 8; nj++) {
                    float p0 = expf(s[nj][0] - mn1);
                    float p1 = expf(s[nj][1] - mn1);
                    float p2 = expf(s[nj][2] - mn2);
                    float p3 = expf(s[nj][3] - mn2);
                    s[nj][0] = p0; s[nj][1] = p1; s[nj][2] = p2; s[nj][3] = p3;
                    ps1 += p0 + p1;
                    ps2 += p2 + p3;
                }
#pragma unroll
                for (int off = 1; off <= 2; off <<= 1) {
                    ps1 += __shfl_xor_sync(0xffffffffu, ps1, off);
                    ps2 += __shfl_xor_sync(0xffffffffu, ps2, off);
                }
                l1 = l1 * al1 + ps1;
                l2 = l2 * al2 + ps2;
#pragma unroll
                for (int nj = 0; nj < 16; nj++) {
                    accO[nj][0] *= al1; accO[nj][1] *= al1;
                    accO[nj][2] *= al2; accO[nj][3] *= al2;
                }

                const uint32_t vbuf = kbuf + 16384;
#pragma unroll
                for (int kv = 0; kv < 4; kv++) {
                    const uint32_t a0 = packh2(s[2 * kv][0],     s[2 * kv][1]);
                    const uint32_t a1 = packh2(s[2 * kv][2],     s[2 * kv][3]);
                    const uint32_t a2 = packh2(s[2 * kv + 1][0], s[2 * kv + 1][1]);
                    const uint32_t a3 = packh2(s[2 * kv + 1][2], s[2 * kv + 1][3]);
#pragma unroll
                    for (int p = 0; p < 8; p++) {
                        const int seg = p >> 2;
                        const uint32_t ro = (uint32_t)((kv * 16 + rV) * 128);
                        uint32_t b0, b1, b2, b3;
                        ldsm4t(b0, b1, b2, b3,
                               vbuf + seg * 8192 + ro
                               + (((uint32_t)((p & 3) * 32 + dbV)) ^ ((ro >> 3) & 0x70)));
                        mma_f16(accO[2 * p],     a0, a1, a2, a3, b0, b1);
                        mma_f16(accO[2 * p + 1], a0, a1, a2, a3, b2, b3);
                    }
                }
            }
            __syncthreads();
        }

        // ---- epilogue for this q-block ----
        const float inv1 = 1.f / l1;
        const float inv2 = 1.f / l2;
        const int row1 = qr0 + (lane >> 2);
        const int colb = head * D_ + (lane & 3) * 2;
#pragma unroll
        for (int nj = 0; nj < 16; nj++) {
            __half2* d1 = (__half2*)(o + (size_t)row1 * H_ + colb + nj * 8);
            __half2* d2 = (__half2*)(o + (size_t)(row1 + 8) * H_ + colb + nj * 8);
            *d1 = __floats2half2_rn(accO[nj][0] * inv1, accO[nj][1] * inv1);
            *d2 = __floats2half2_rn(accO[nj][2] * inv2, accO[nj][3] * inv2);
        }
    }
#undef LOADKV
}

// ---------------- launch ----------------
extern "C" void kernel_launch(void* const* d_in, const int* in_sizes, int n_in,
                              void* d_out, int out_size)
{
    (void)in_sizes; (void)n_in; (void)out_size;
    const float* x      = (const float*)d_in[0];
    const int*   pos    = (const int*)  d_in[1];
    const float* w_q    = (const float*)d_in[2];
    const float* w_k    = (const float*)d_in[3];
    const float* w_v    = (const float*)d_in[4];
    const float* w_o    = (const float*)d_in[5];
    const float* w_gate = (const float*)d_in[6];
    const float* w_up   = (const float*)d_in[7];
    const float* w_down = (const float*)d_in[8];
    const float* rms1   = (const float*)d_in[9];
    const float* rms2   = (const float*)d_in[10];
    float* out = (float*)d_out;

    __half *h, *attn, *gu, *qh, *kh, *vh, *gate, *wqkv, *wo, *wg, *wu, *wd;
    float *x1;
    cudaGetSymbolAddress((void**)&h,    g_h);
    cudaGetSymbolAddress((void**)&qh,   g_qh);
    cudaGetSymbolAddress((void**)&kh,   g_kh);
    cudaGetSymbolAddress((void**)&vh,   g_vh);
    cudaGetSymbolAddress((void**)&attn, g_attn);
    cudaGetSymbolAddress((void**)&x1,   g_x1);
    cudaGetSymbolAddress((void**)&gate, g_gate);
    cudaGetSymbolAddress((void**)&gu,   g_gu);
    cudaGetSymbolAddress((void**)&wqkv, g_wqkv);
    cudaGetSymbolAddress((void**)&wo,   g_wo);
    cudaGetSymbolAddress((void**)&wg,   g_wg);
    cudaGetSymbolAddress((void**)&wu,   g_wu);
    cudaGetSymbolAddress((void**)&wd,   g_wd);

    cudaFuncSetAttribute(attn16_kernel, cudaFuncAttributeMaxDynamicSharedMemorySize, ATT_SMEM);
    cudaFuncSetAttribute(gemm_f16_kernel<1,0>, cudaFuncAttributeMaxDynamicSharedMemorySize, GEMM_SMEM);
    cudaFuncSetAttribute(gemm_f16_kernel<2,1>, cudaFuncAttributeMaxDynamicSharedMemorySize, GEMM_SMEM);
    cudaFuncSetAttribute(gemm_f16_kernel<3,1>, cudaFuncAttributeMaxDynamicSharedMemorySize, GEMM_SMEM);
    cudaFuncSetAttribute(gemm_f16_kernel<4,0>, cudaFuncAttributeMaxDynamicSharedMemorySize, GEMM_SMEM);

    // 0. ALL weights -> fp16 in ONE launch (big-first segment order)
    {
        long nblk = (S_TOTAL + 255) / 256;
        f2h_all_kernel<<<(unsigned)nblk, 256>>>(
            (const float4*)w_q, (const float4*)w_k, (const float4*)w_v,
            (const float4*)w_o, (const float4*)w_gate, (const float4*)w_up,
            (const float4*)w_down,
            (__half2*)wqkv, (__half2*)wo, (__half2*)wg, (__half2*)wu, (__half2*)wd);
    }

    // 1. h = rmsnorm(x) * rms1  (fp16)
    rmsnorm_kernel<<<T_, 256>>>(x, rms1, h);
    // 2. fused QKV projection -> qh, kh, vh (all fp16)
    gemm_f16_kernel<4,0><<<dim3(48, T_ / 128), 256, GEMM_SMEM>>>(h, wqkv, nullptr, qh, kh, vh, 0, H_);
    // 3. fused RoPE in-place on fp16 q/k
    rope2_kernel<<<dim3(T_, (HQ_ + HKV_) / 4), 256>>>(qh, kh, pos);
    // 4. causal attention (fp16 tensor cores, balanced)
    attn16_kernel<<<dim3(8, HQ_), 256, ATT_SMEM>>>(qh, kh, vh, attn);
    // 5. x1 = x + attn @ w_o^T
    gemm_f16_kernel<1,0><<<dim3(H_ / 128, T_ / 128), 256, GEMM_SMEM>>>(attn, wo, x, x1, nullptr, nullptr, H_, H_);
    // 6. h = rmsnorm(x1) * rms2 (fp16)
    rmsnorm_kernel<<<T_, 256>>>(x1, rms2, h);
    // 7. gate = silu(h @ w_gate^T)  (fp16)
    gemm_f16_kernel<2,1><<<dim3(I_ / 128, T_ / 128), 256, GEMM_SMEM>>>(h, wg, nullptr, gate, nullptr, nullptr, I_, H_);
    // 8. gu = gate * (h @ w_up^T)  (fp16)
    gemm_f16_kernel<3,1><<<dim3(I_ / 128, T_ / 128), 256, GEMM_SMEM>>>(h, wu, gate, gu, nullptr, nullptr, I_, H_);
    // 9. out = x1 + gu @ w_down^T
    gemm_f16_kernel<1,0><<<dim3(H_ / 128, T_ / 128), 256, GEMM_SMEM>>>(gu, wd, x1, out, nullptr, nullptr, H_, I_);
}

// round 14
// speedup vs baseline: 1.5242x; 1.5242x over previous
#include <cuda_runtime.h>
#include <cuda_fp16.h>
#include <cstddef>
#include <cstdint>
#include <math.h>

// ---------------- problem constants ----------------
#define T_  2048
#define H_  4096
#define HQ_ 32
#define HKV_ 8
#define D_  128
#define I_  14336

// ---------------- scratch (device globals; no allocation allowed) ----------------
__device__ __half g_h   [T_ * H_];            // rmsnorm out (fp16)
__device__ float  g_q   [T_ * HQ_ * D_];      // q proj fp32 (pre-rope)
__device__ float  g_k   [T_ * HKV_ * D_];     // k proj fp32 (pre-rope)
__device__ __half g_qh  [T_ * HQ_ * D_];      // q fp16 post-rope
__device__ __half g_kh  [T_ * HKV_ * D_];     // k fp16 post-rope
__device__ __half g_vh  [T_ * HKV_ * D_];     // v fp16
__device__ __half g_attn[T_ * H_];            // attention out (fp16)
__device__ float  g_x1  [T_ * H_];
__device__ __half g_gate[T_ * (size_t)I_];
__device__ __half g_gu  [T_ * (size_t)I_];
// fp16 weight copies (qkv concatenated: wq 4096 rows | wk 1024 | wv 1024)
__device__ __half g_wqkv[(size_t)(H_ + 2 * HKV_ * D_) * H_];
__device__ __half g_wo[(size_t)H_ * H_];
__device__ __half g_wg[(size_t)I_ * H_];
__device__ __half g_wu[(size_t)I_ * H_];
__device__ __half g_wd[(size_t)H_ * I_];

// ---------------- helpers ----------------
__device__ __forceinline__ uint32_t smem_u32(const void* p) {
    return (uint32_t)__cvta_generic_to_shared(p);
}
__device__ __forceinline__ void cp_async16(uint32_t saddr, const void* gmem) {
    asm volatile("cp.async.cg.shared.global [%0], [%1], 16;\n" :: "r"(saddr), "l"(gmem));
}
#define CP_COMMIT() asm volatile("cp.async.commit_group;\n" ::: "memory")

__device__ __forceinline__ void ldsm4(uint32_t& r0, uint32_t& r1, uint32_t& r2,
                                      uint32_t& r3, uint32_t addr) {
    asm volatile("ldmatrix.sync.aligned.m8n8.x4.shared.b16 {%0,%1,%2,%3}, [%4];"
                 : "=r"(r0), "=r"(r1), "=r"(r2), "=r"(r3) : "r"(addr));
}
__device__ __forceinline__ void ldsm4t(uint32_t& r0, uint32_t& r1, uint32_t& r2,
                                       uint32_t& r3, uint32_t addr) {
    asm volatile("ldmatrix.sync.aligned.m8n8.x4.trans.shared.b16 {%0,%1,%2,%3}, [%4];"
                 : "=r"(r0), "=r"(r1), "=r"(r2), "=r"(r3) : "r"(addr));
}
__device__ __forceinline__ void mma_f16(float* c,
    uint32_t a0, uint32_t a1, uint32_t a2, uint32_t a3, uint32_t b0, uint32_t b1)
{
    asm volatile(
        "mma.sync.aligned.m16n8k16.row.col.f32.f16.f16.f32 "
        "{%0,%1,%2,%3}, {%4,%5,%6,%7}, {%8,%9}, {%0,%1,%2,%3};"
        : "+f"(c[0]), "+f"(c[1]), "+f"(c[2]), "+f"(c[3])
        : "r"(a0), "r"(a1), "r"(a2), "r"(a3), "r"(b0), "r"(b1));
}
__device__ __forceinline__ uint32_t packh2(float a, float b) {
    __half2 h = __floats2half2_rn(a, b);
    return *(uint32_t*)&h;
}

// ---------------- fused weight convert fp32 -> fp16 (ONE launch) ----------------
#define S_WQ 4194304L
#define S_WK 1048576L
#define S_WV 1048576L
#define S_WO 4194304L
#define S_WG 14680064L
#define S_WU 14680064L
#define S_WD 14680064L
#define S_TOTAL (S_WQ + S_WK + S_WV + S_WO + S_WG + S_WU + S_WD)

__global__ void __launch_bounds__(256) f2h_all_kernel(
    const float4* __restrict__ wq, const float4* __restrict__ wk,
    const float4* __restrict__ wv, const float4* __restrict__ wo,
    const float4* __restrict__ wg, const float4* __restrict__ wu,
    const float4* __restrict__ wd,
    __half2* __restrict__ dqkv, __half2* __restrict__ dwo,
    __half2* __restrict__ dwg, __half2* __restrict__ dwu,
    __half2* __restrict__ dwd)
{
    long i = (long)blockIdx.x * 256 + threadIdx.x;
    if (i >= S_TOTAL) return;
    const float4* src;
    __half2* dst;
    long j = i;
    if (j < S_WQ)                      { src = wq; dst = dqkv; }
    else if ((j -= S_WQ) < S_WK)       { src = wk; dst = dqkv + 2 * S_WQ; }
    else if ((j -= S_WK) < S_WV)       { src = wv; dst = dqkv + 2 * (S_WQ + S_WK); }
    else if ((j -= S_WV) < S_WO)       { src = wo; dst = dwo; }
    else if ((j -= S_WO) < S_WG)       { src = wg; dst = dwg; }
    else if ((j -= S_WG) < S_WU)       { src = wu; dst = dwu; }
    else                { j -= S_WU;     src = wd; dst = dwd; }
    float4 v = src[j];
    dst[2 * j]     = __floats2half2_rn(v.x, v.y);
    dst[2 * j + 1] = __floats2half2_rn(v.z, v.w);
}

// ---------------- RMSNorm (fp16 output) ----------------
__global__ void __launch_bounds__(256) rmsnorm_kernel(
    const float* __restrict__ x, const float* __restrict__ w, __half* __restrict__ out)
{
    const int row = blockIdx.x;
    const float4* xv = (const float4*)(x + (size_t)row * H_);
    const float4* wv = (const float4*)w;
    __half2* ov = (__half2*)(out + (size_t)row * H_);

    float4 buf[4];
    float ss = 0.f;
#pragma unroll
    for (int i = 0; i < 4; i++) {
        float4 v = xv[threadIdx.x + i * 256];
        buf[i] = v;
        ss += v.x * v.x + v.y * v.y + v.z * v.z + v.w * v.w;
    }
#pragma unroll
    for (int o = 16; o; o >>= 1) ss += __shfl_xor_sync(0xffffffffu, ss, o);

    __shared__ float wsum[8];
    __shared__ float s_inv;
    if ((threadIdx.x & 31) == 0) wsum[threadIdx.x >> 5] = ss;
    __syncthreads();
    if (threadIdx.x == 0) {
        float tot = 0.f;
#pragma unroll
        for (int i = 0; i < 8; i++) tot += wsum[i];
        s_inv = rsqrtf(tot * (1.f / (float)H_) + 1e-5f);
    }
    __syncthreads();
    const float inv = s_inv;
#pragma unroll
    for (int i = 0; i < 4; i++) {
        float4 v = buf[i];
        float4 ww = wv[threadIdx.x + i * 256];
        ov[(threadIdx.x + i * 256) * 2]     = __floats2half2_rn(v.x * inv * ww.x, v.y * inv * ww.y);
        ov[(threadIdx.x + i * 256) * 2 + 1] = __floats2half2_rn(v.z * inv * ww.z, v.w * inv * ww.w);
    }
}

// ---------------- fused RoPE (q + k): fp32 in, fp16 out, 4 heads/block ----------------
__global__ void __launch_bounds__(256) rope2_kernel(
    const float* __restrict__ qi, const float* __restrict__ ki,
    const int* __restrict__ pos,
    __half* __restrict__ qo, __half* __restrict__ ko)
{
    const int tt = blockIdx.x;
    int h = blockIdx.y * 4 + (threadIdx.x >> 6);   // 0..39
    const int j = threadIdx.x & 63;
    const float p = (float)pos[tt];
    const float invf = expf(-(float)j * 0.20503692777194262f);
    float s, c;
    sincosf(p * invf, &s, &c);
    const float* base;
    __half* ob;
    if (h < HQ_) {
        base = qi + ((size_t)tt * HQ_ + h) * D_ + j;
        ob   = qo + ((size_t)tt * HQ_ + h) * D_ + j;
    } else {
        h -= HQ_;
        base = ki + ((size_t)tt * HKV_ + h) * D_ + j;
        ob   = ko + ((size_t)tt * HKV_ + h) * D_ + j;
    }
    const float x1v = base[0];
    const float x2v = base[64];
    ob[0]  = __float2half(x1v * c - x2v * s);
    ob[64] = __float2half(x2v * c + x1v * s);
}

// ---------------- fp16 tensor-core GEMM: C[M,N] = A[M,K] * B[N,K]^T ----------------
// ROUND-9 CONFIG (empirical optimum): 256 thr, 8 warps 2x4, warp 64x32,
// 3-stage cp.async, single barrier per k-tile, 2 CTAs/SM, grid = (N/128, M/128).
// MODE 0: store  1: C=Cin(f32)+acc  2: C=silu(acc)  3: C=Cin(f16)*acc  4: QKV split
// OUTH: 1 -> fp16 output, 0 -> fp32 output
#define STAGE_A 16384
#define STAGE_BYTES 32768
#define GEMM_SMEM (3 * STAGE_BYTES)

template <int MODE, int OUTH>
__global__ void __launch_bounds__(256, 2) gemm_f16_kernel(
    const __half* __restrict__ A, const __half* __restrict__ B,
    const void* __restrict__ Cin, void* __restrict__ Cv,
    void* __restrict__ Cv2, void* __restrict__ Cv3, int N, int K)
{
    extern __shared__ __align__(1024) char smem[];
    const uint32_t sbase = smem_u32(smem);
    const int tid  = threadIdx.x;
    const int wid  = tid >> 5;
    const int lane = tid & 31;
    const int warpM = (wid >> 2) * 64;
    const int warpN = (wid & 3) * 32;
    const size_t arow0 = (size_t)blockIdx.y * 128;
    const size_t brow0 = (size_t)blockIdx.x * 128;
    const int ntiles = K >> 6;

    const int lrow = tid >> 1;
    const int lch  = (tid & 1) * 4;
    const __half* Ag = A + (arow0 + lrow) * K + lch * 8;
    const __half* Bg = B + (brow0 + lrow) * K + lch * 8;
    uint32_t s_off[4];
#pragma unroll
    for (int i = 0; i < 4; i++) {
        uint32_t o = (uint32_t)(lrow * 128 + (lch + i) * 16);
        s_off[i] = o ^ ((o >> 3) & 0x70);
    }

#define LOADT(t, slot)                                                   \
    {                                                                    \
        const uint32_t sa = sbase + (slot) * STAGE_BYTES;                \
        const __half* ag = Ag + (size_t)(t) * 64;                        \
        const __half* bg = Bg + (size_t)(t) * 64;                        \
        _Pragma("unroll")                                                \
        for (int i = 0; i < 4; i++) {                                    \
            cp_async16(sa + s_off[i], ag + i * 8);                       \
            cp_async16(sa + STAGE_A + s_off[i], bg + i * 8);             \
        }                                                                \
    }

    uint32_t aRow[4], aMask[4], bRow[2], bMask[2];
    const int kbA = (lane >> 4) * 16;
    {
        const int r = lane & 15;
#pragma unroll
        for (int mi = 0; mi < 4; mi++) {
            uint32_t o = (uint32_t)((warpM + mi * 16 + r) * 128);
            aRow[mi]  = o;
            aMask[mi] = (o >> 3) & 0x70;
        }
    }
    const int rn  = (lane & 7) + ((lane >> 4) << 3);
    const int kbB = ((lane >> 3) & 1) * 16;
    {
#pragma unroll
        for (int ni = 0; ni < 2; ni++) {
            uint32_t o = (uint32_t)((warpN + ni * 16 + rn) * 128);
            bRow[ni]  = o;
            bMask[ni] = (o >> 3) & 0x70;
        }
    }

    float acc[4][4][4];
#pragma unroll
    for (int mi = 0; mi < 4; mi++)
#pragma unroll
        for (int nj = 0; nj < 4; nj++)
#pragma unroll
            for (int r = 0; r < 4; r++) acc[mi][nj][r] = 0.f;

    LOADT(0, 0); CP_COMMIT();
    LOADT(1, 1); CP_COMMIT();

    for (int t = 0; t < ntiles; t++) {
        asm volatile("cp.async.wait_group 1;\n" ::: "memory");
        __syncthreads();
        if (t + 2 < ntiles) { LOADT(t + 2, (t + 2) % 3); }
        CP_COMMIT();

        const uint32_t sa = sbase + (t % 3) * STAGE_BYTES;
#pragma unroll
        for (int ks = 0; ks < 4; ks++) {
            uint32_t b[2][4];
#pragma unroll
            for (int ni = 0; ni < 2; ni++)
                ldsm4(b[ni][0], b[ni][1], b[ni][2], b[ni][3],
                      sa + STAGE_A + bRow[ni] + (((uint32_t)(kbB + ks * 32)) ^ bMask[ni]));
#pragma unroll
            for (int mi = 0; mi < 4; mi++) {
                uint32_t a0, a1, a2, a3;
                ldsm4(a0, a1, a2, a3,
                      sa + aRow[mi] + (((uint32_t)(kbA + ks * 32)) ^ aMask[mi]));
#pragma unroll
                for (int nj = 0; nj < 4; nj++)
                    mma_f16(acc[mi][nj], a0, a1, a2, a3,
                            b[nj >> 1][(nj & 1) * 2], b[nj >> 1][(nj & 1) * 2 + 1]);
            }
        }
    }
#undef LOADT

    // epilogue
    const int r0 = (int)arow0 + warpM + (lane >> 2);
    if (MODE == 4) {
        const int gcol0 = blockIdx.x * 128 + warpN + (lane & 3) * 2;
        float* outF = nullptr;
        __half* outH = nullptr;
        int Nout, col0;
        if (gcol0 < 4096)      { outF = (float*)Cv;  Nout = H_;         col0 = gcol0; }
        else if (gcol0 < 5120) { outF = (float*)Cv2; Nout = HKV_ * D_;  col0 = gcol0 - 4096; }
        else                   { outH = (__half*)Cv3; Nout = HKV_ * D_; col0 = gcol0 - 5120; }
#pragma unroll
        for (int mi = 0; mi < 4; mi++) {
#pragma unroll
            for (int h = 0; h < 2; h++) {
                const int row = r0 + mi * 16 + h * 8;
#pragma unroll
                for (int nj = 0; nj < 4; nj++) {
                    const int col = col0 + nj * 8;
                    float vx = acc[mi][nj][h * 2 + 0];
                    float vy = acc[mi][nj][h * 2 + 1];
                    if (outF) {
                        *(float2*)(outF + (size_t)row * Nout + col) = make_float2(vx, vy);
                    } else {
                        *(__half2*)(outH + (size_t)row * Nout + col) = __floats2half2_rn(vx, vy);
                    }
                }
            }
        }
        return;
    }

    const int c0 = blockIdx.x * 128 + warpN + (lane & 3) * 2;
#pragma unroll
    for (int mi = 0; mi < 4; mi++) {
#pragma unroll
        for (int h = 0; h < 2; h++) {
            const int row = r0 + mi * 16 + h * 8;
#pragma unroll
            for (int nj = 0; nj < 4; nj++) {
                const int col = c0 + nj * 8;
                float vx = acc[mi][nj][h * 2 + 0];
                float vy = acc[mi][nj][h * 2 + 1];
                if (MODE == 1) {
                    const float* cin = (const float*)Cin + (size_t)row * N + col;
                    vx += cin[0];
                    vy += cin[1];
                } else if (MODE == 2) {
                    vx = vx / (1.f + expf(-vx));
                    vy = vy / (1.f + expf(-vy));
                } else if (MODE == 3) {
                    const __half2 c2 = *(const __half2*)((const __half*)Cin + (size_t)row * N + col);
                    const float2 cf = __half22float2(c2);
                    vx *= cf.x;
                    vy *= cf.y;
                }
                if (OUTH) {
                    __half2* dst = (__half2*)((__half*)Cv + (size_t)row * N + col);
                    *dst = __floats2half2_rn(vx, vy);
                } else {
                    float2* dst = (float2*)((float*)Cv + (size_t)row * N + col);
                    *dst = make_float2(vx, vy);
                }
            }
        }
    }
}

// ---------------- fp16 tensor-core causal flash attention ----------------
// grid (8, HQ): CTA bx processes q-blocks {bx, 15-bx} -> uniform 32 KV-tiles per CTA.
#define AQ_OFF   0
#define AKV_OFF  32768
#define AKV_STRIDE 32768
#define ATT_SMEM (32768 + 2 * AKV_STRIDE)   // 96KB

__global__ void __launch_bounds__(256) attn16_kernel(
    const __half* __restrict__ qh, const __half* __restrict__ kh,
    const __half* __restrict__ vh, __half* __restrict__ o)
{
    extern __shared__ __align__(1024) char smem[];
    const uint32_t sbase = smem_u32(smem);
    const int tid  = threadIdx.x;
    const int wid  = tid >> 5;
    const int lane = tid & 31;
    const int bx   = blockIdx.x;        // 0..7
    const int head = blockIdx.y;
    const int kvh  = head >> 2;
    const float scale = 0.08838834764831845f;

    const int rA    = lane & 15;
    const int kbA   = (lane >> 4) * 16;
    const int rnB   = (lane & 7) + ((lane >> 4) << 3);
    const int kbB   = ((lane >> 3) & 1) * 16;
    const int rV    = (lane & 7) + ((lane >> 3) & 1) * 8;
    const int dbV   = ((lane >> 4) & 1) * 16;

#define LOADKV(kt, buf)                                                              \
    {                                                                                \
        const int k0l = (kt) * 64;                                                   \
        const uint32_t kb = sbase + AKV_OFF + (buf) * AKV_STRIDE;                    \
        _Pragma("unroll")                                                            \
        for (int i = 0; i < 4; i++) {                                                \
            const int chunk = tid + 256 * i;                                         \
            const int seg = chunk >> 9;                                              \
            const int row = (chunk >> 3) & 63;                                       \
            const int off = chunk & 7;                                               \
            const uint32_t ro = (uint32_t)(row * 128);                               \
            const uint32_t sw = ro + (((uint32_t)(off * 16)) ^ ((ro >> 3) & 0x70));  \
            const size_t gi = (size_t)(k0l + row) * (HKV_ * D_) + kvh * D_           \
                            + seg * 64 + off * 8;                                    \
            cp_async16(kb + seg * 8192 + sw, kh + gi);                               \
            cp_async16(kb + 16384 + seg * 8192 + sw, vh + gi);                       \
        }                                                                            \
    }

#pragma unroll 1
    for (int it = 0; it < 2; it++) {
        const int qblk = (it == 0) ? bx : (15 - bx);
        const int q0   = qblk * 128;
        const int qr0  = q0 + wid * 16;

        // ---- load Q tile ----
#pragma unroll
        for (int i = 0; i < 8; i++) {
            const int chunk = tid + 256 * i;
            const int seg = chunk >> 10;
            const int row = (chunk >> 3) & 127;
            const int off = chunk & 7;
            const uint32_t ro = (uint32_t)(row * 128);
            const uint32_t sw = ro + (((uint32_t)(off * 16)) ^ ((ro >> 3) & 0x70));
            cp_async16(sbase + AQ_OFF + seg * 16384 + sw,
                       qh + (size_t)(q0 + row) * (HQ_ * D_) + head * D_ + seg * 64 + off * 8);
        }
        CP_COMMIT();
        LOADKV(0, 0); CP_COMMIT();

        uint32_t qf[8][4];
        float accO[16][4];
#pragma unroll
        for (int nj = 0; nj < 16; nj++)
#pragma unroll
            for (int r = 0; r < 4; r++) accO[nj][r] = 0.f;
        float m1 = -1e30f, m2 = -1e30f, l1 = 0.f, l2 = 0.f;

        const int ktmax = 2 * qblk + 1;
        for (int kt = 0; kt <= ktmax; kt++) {
            if (kt < ktmax) {
                LOADKV(kt + 1, (kt + 1) & 1);
                CP_COMMIT();
                asm volatile("cp.async.wait_group 1;\n" ::: "memory");
            } else {
                asm volatile("cp.async.wait_group 0;\n" ::: "memory");
            }
            __syncthreads();

            if (kt == 0) {
#pragma unroll
                for (int ks = 0; ks < 8; ks++) {
                    const int seg = ks >> 2;
                    const uint32_t ro = (uint32_t)((wid * 16 + rA) * 128);
                    const uint32_t addr = sbase + AQ_OFF + seg * 16384 + ro
                        + (((uint32_t)(kbA + (ks & 3) * 32)) ^ ((ro >> 3) & 0x70));
                    ldsm4(qf[ks][0], qf[ks][1], qf[ks][2], qf[ks][3], addr);
                }
            }

            const int k0 = kt * 64;
            if (k0 <= qr0 + 15) {
                const uint32_t kbuf = sbase + AKV_OFF + (kt & 1) * AKV_STRIDE;
                float s[8][4];
#pragma unroll
                for (int nj = 0; nj < 8; nj++)
#pragma unroll
                    for (int r = 0; r < 4; r++) s[nj][r] = 0.f;

#pragma unroll
                for (int ks = 0; ks < 8; ks++) {
                    const int seg = ks >> 2;
                    uint32_t b[4][4];
#pragma unroll
                    for (int ni = 0; ni < 4; ni++) {
                        const uint32_t ro = (uint32_t)((ni * 16 + rnB) * 128);
                        ldsm4(b[ni][0], b[ni][1], b[ni][2], b[ni][3],
                              kbuf + seg * 8192 + ro
                              + (((uint32_t)(kbB + (ks & 3) * 32)) ^ ((ro >> 3) & 0x70)));
                    }
#pragma unroll
                    for (int nj = 0; nj < 8; nj++)
                        mma_f16(s[nj], qf[ks][0], qf[ks][1], qf[ks][2], qf[ks][3],
                                b[nj >> 1][(nj & 1) * 2], b[nj >> 1][(nj & 1) * 2 + 1]);
                }

                const int row1 = qr0 + (lane >> 2);
                const int row2 = row1 + 8;
                float rmax1 = -1e30f, rmax2 = -1e30f;
#pragma unroll
                for (int nj = 0; nj < 8; nj++) {
                    const int c0 = k0 + nj * 8 + (lane & 3) * 2;
                    float v0 = s[nj][0] * scale, v1 = s[nj][1] * scale;
                    float v2 = s[nj][2] * scale, v3 = s[nj][3] * scale;
                    if (c0 > row1)     v0 = -1e30f;
                    if (c0 + 1 > row1) v1 = -1e30f;
                    if (c0 > row2)     v2 = -1e30f;
                    if (c0 + 1 > row2) v3 = -1e30f;
                    s[nj][0] = v0; s[nj][1] = v1; s[nj][2] = v2; s[nj][3] = v3;
                    rmax1 = fmaxf(rmax1, fmaxf(v0, v1));
                    rmax2 = fmaxf(rmax2, fmaxf(v2, v3));
                }
#pragma unroll
                for (int off = 1; off <= 2; off <<= 1) {
                    rmax1 = fmaxf(rmax1, __shfl_xor_sync(0xffffffffu, rmax1, off));
                    rmax2 = fmaxf(rmax2, __shfl_xor_sync(0xffffffffu, rmax2, off));
                }
                const float mn1 = fmaxf(m1, rmax1);
                const float mn2 = fmaxf(m2, rmax2);
                const float al1 = expf(m1 - mn1);
                const float al2 = expf(m2 - mn2);
                m1 = mn1; m2 = mn2;

                float ps1 = 0.f, ps2 = 0.f;
#pragma unroll
                for (int nj = 0; nj < 8; nj++) {
                    float p0 = expf(s[nj][0] - mn1);
                    float p1 = expf(s[nj][1] - mn1);
                    float p2 = expf(s[nj][2] - mn2);
                    float p3 = expf(s[nj][3] - mn2);
                    s[nj][0] = p0; s[nj][1] = p1; s[nj][2] = p2; s[nj][3] = p3;
                    ps1 += p0 + p1;
                    ps2 += p2 + p3;
                }
#pragma unroll
                for (int off = 1; off <= 2; off <<= 1) {
                    ps1 += __shfl_xor_sync(0xffffffffu, ps1, off);
                    ps2 += __shfl_xor_sync(0xffffffffu, ps2, off);
                }
                l1 = l1 * al1 + ps1;
                l2 = l2 * al2 + ps2;
#pragma unroll
                for (int nj = 0; nj < 16; nj++) {
                    accO[nj][0] *= al1; accO[nj][1] *= al1;
                    accO[nj][2] *= al2; accO[nj][3] *= al2;
                }

                const uint32_t vbuf = kbuf + 16384;
#pragma unroll
                for (int kv = 0; kv < 4; kv++) {
                    const uint32_t a0 = packh2(s[2 * kv][0],     s[2 * kv][1]);
                    const uint32_t a1 = packh2(s[2 * kv][2],     s[2 * kv][3]);
                    const uint32_t a2 = packh2(s[2 * kv + 1][0], s[2 * kv + 1][1]);
                    const uint32_t a3 = packh2(s[2 * kv + 1][2], s[2 * kv + 1][3]);
#pragma unroll
                    for (int p = 0; p < 8; p++) {
                        const int seg = p >> 2;
                        const uint32_t ro = (uint32_t)((kv * 16 + rV) * 128);
                        uint32_t b0, b1, b2, b3;
                        ldsm4t(b0, b1, b2, b3,
                               vbuf + seg * 8192 + ro
                               + (((uint32_t)((p & 3) * 32 + dbV)) ^ ((ro >> 3) & 0x70)));
                        mma_f16(accO[2 * p],     a0, a1, a2, a3, b0, b1);
                        mma_f16(accO[2 * p + 1], a0, a1, a2, a3, b2, b3);
                    }
                }
            }
            __syncthreads();
        }

        // ---- epilogue for this q-block ----
        const float inv1 = 1.f / l1;
        const float inv2 = 1.f / l2;
        const int row1 = qr0 + (lane >> 2);
        const int colb = head * D_ + (lane & 3) * 2;
#pragma unroll
        for (int nj = 0; nj < 16; nj++) {
            __half2* d1 = (__half2*)(o + (size_t)row1 * H_ + colb + nj * 8);
            __half2* d2 = (__half2*)(o + (size_t)(row1 + 8) * H_ + colb + nj * 8);
            *d1 = __floats2half2_rn(accO[nj][0] * inv1, accO[nj][1] * inv1);
            *d2 = __floats2half2_rn(accO[nj][2] * inv2, accO[nj][3] * inv2);
        }
    }
#undef LOADKV
}

// ---------------- launch ----------------
extern "C" void kernel_launch(void* const* d_in, const int* in_sizes, int n_in,
                              void* d_out, int out_size)
{
    (void)in_sizes; (void)n_in; (void)out_size;
    const float* x      = (const float*)d_in[0];
    const int*   pos    = (const int*)  d_in[1];
    const float* w_q    = (const float*)d_in[2];
    const float* w_k    = (const float*)d_in[3];
    const float* w_v    = (const float*)d_in[4];
    const float* w_o    = (const float*)d_in[5];
    const float* w_gate = (const float*)d_in[6];
    const float* w_up   = (const float*)d_in[7];
    const float* w_down = (const float*)d_in[8];
    const float* rms1   = (const float*)d_in[9];
    const float* rms2   = (const float*)d_in[10];
    float* out = (float*)d_out;

    __half *h, *attn, *gu, *qh, *kh, *vh, *gate, *wqkv, *wo, *wg, *wu, *wd;
    float *q, *k, *x1;
    cudaGetSymbolAddress((void**)&h,    g_h);
    cudaGetSymbolAddress((void**)&q,    g_q);
    cudaGetSymbolAddress((void**)&k,    g_k);
    cudaGetSymbolAddress((void**)&qh,   g_qh);
    cudaGetSymbolAddress((void**)&kh,   g_kh);
    cudaGetSymbolAddress((void**)&vh,   g_vh);
    cudaGetSymbolAddress((void**)&attn, g_attn);
    cudaGetSymbolAddress((void**)&x1,   g_x1);
    cudaGetSymbolAddress((void**)&gate, g_gate);
    cudaGetSymbolAddress((void**)&gu,   g_gu);
    cudaGetSymbolAddress((void**)&wqkv, g_wqkv);
    cudaGetSymbolAddress((void**)&wo,   g_wo);
    cudaGetSymbolAddress((void**)&wg,   g_wg);
    cudaGetSymbolAddress((void**)&wu,   g_wu);
    cudaGetSymbolAddress((void**)&wd,   g_wd);

    cudaFuncSetAttribute(attn16_kernel, cudaFuncAttributeMaxDynamicSharedMemorySize, ATT_SMEM);
    cudaFuncSetAttribute(gemm_f16_kernel<1,0>, cudaFuncAttributeMaxDynamicSharedMemorySize, GEMM_SMEM);
    cudaFuncSetAttribute(gemm_f16_kernel<2,1>, cudaFuncAttributeMaxDynamicSharedMemorySize, GEMM_SMEM);
    cudaFuncSetAttribute(gemm_f16_kernel<3,1>, cudaFuncAttributeMaxDynamicSharedMemorySize, GEMM_SMEM);
    cudaFuncSetAttribute(gemm_f16_kernel<4,0>, cudaFuncAttributeMaxDynamicSharedMemorySize, GEMM_SMEM);

    // 0. ALL weights -> fp16 in ONE launch
    {
        long nblk = (S_TOTAL + 255) / 256;
        f2h_all_kernel<<<(unsigned)nblk, 256>>>(
            (const float4*)w_q, (const float4*)w_k, (const float4*)w_v,
            (const float4*)w_o, (const float4*)w_gate, (const float4*)w_up,
            (const float4*)w_down,
            (__half2*)wqkv, (__half2*)wo, (__half2*)wg, (__half2*)wu, (__half2*)wd);
    }

    // 1. h = rmsnorm(x) * rms1  (fp16)
    rmsnorm_kernel<<<T_, 256>>>(x, rms1, h);
    // 2. fused QKV projection (q fp32, k fp32, v fp16), N=6144
    gemm_f16_kernel<4,0><<<dim3(48, T_ / 128), 256, GEMM_SMEM>>>(h, wqkv, nullptr, q, k, vh, 0, H_);
    // 3. fused RoPE (fp32 -> fp16), 4 heads per block
    rope2_kernel<<<dim3(T_, (HQ_ + HKV_) / 4), 256>>>(q, k, pos, qh, kh);
    // 4. causal attention (fp16 tensor cores, balanced)
    attn16_kernel<<<dim3(8, HQ_), 256, ATT_SMEM>>>(qh, kh, vh, attn);
    // 5. x1 = x + attn @ w_o^T
    gemm_f16_kernel<1,0><<<dim3(H_ / 128, T_ / 128), 256, GEMM_SMEM>>>(attn, wo, x, x1, nullptr, nullptr, H_, H_);
    // 6. h = rmsnorm(x1) * rms2 (fp16)
    rmsnorm_kernel<<<T_, 256>>>(x1, rms2, h);
    // 7. gate = silu(h @ w_gate^T)  (fp16)
    gemm_f16_kernel<2,1><<<dim3(I_ / 128, T_ / 128), 256, GEMM_SMEM>>>(h, wg, nullptr, gate, nullptr, nullptr, I_, H_);
    // 8. gu = gate * (h @ w_up^T)  (fp16)
    gemm_f16_kernel<3,1><<<dim3(I_ / 128, T_ / 128), 256, GEMM_SMEM>>>(h, wu, gate, gu, nullptr, nullptr, I_, H_);
    // 9. out = x1 + gu @ w_down^T
    gemm_f16_kernel<1,0><<<dim3(H_ / 128, T_ / 128), 256, GEMM_SMEM>>>(gu, wd, x1, out, nullptr, nullptr, H_, I_);
}

// round 15
// speedup vs baseline: 1.5362x; 1.0079x over previous
#include <cuda_runtime.h>
#include <cuda_fp16.h>
#include <cstddef>
#include <cstdint>
#include <math.h>

// ---------------- problem constants ----------------
#define T_  2048
#define H_  4096
#define HQ_ 32
#define HKV_ 8
#define D_  128
#define I_  14336

// ---------------- scratch (device globals; no allocation allowed) ----------------
__device__ __half g_h   [T_ * H_];            // rmsnorm out (fp16)
__device__ float  g_q   [T_ * HQ_ * D_];      // q proj fp32 (pre-rope)
__device__ float  g_k   [T_ * HKV_ * D_];     // k proj fp32 (pre-rope)
__device__ __half g_qh  [T_ * HQ_ * D_];      // q fp16 post-rope
__device__ __half g_kh  [T_ * HKV_ * D_];     // k fp16 post-rope
__device__ __half g_vh  [T_ * HKV_ * D_];     // v fp16
__device__ __half g_attn[T_ * H_];            // attention out (fp16)
__device__ float  g_x1  [T_ * H_];
__device__ __half g_gate[T_ * (size_t)I_];
__device__ __half g_gu  [T_ * (size_t)I_];
// fp16 weight copies (qkv concatenated: wq 4096 rows | wk 1024 | wv 1024)
__device__ __half g_wqkv[(size_t)(H_ + 2 * HKV_ * D_) * H_];
__device__ __half g_wo[(size_t)H_ * H_];
__device__ __half g_wg[(size_t)I_ * H_];
__device__ __half g_wu[(size_t)I_ * H_];
__device__ __half g_wd[(size_t)H_ * I_];

// ---------------- helpers ----------------
__device__ __forceinline__ uint32_t smem_u32(const void* p) {
    return (uint32_t)__cvta_generic_to_shared(p);
}
__device__ __forceinline__ void cp_async16(uint32_t saddr, const void* gmem) {
    asm volatile("cp.async.cg.shared.global [%0], [%1], 16;\n" :: "r"(saddr), "l"(gmem));
}
#define CP_COMMIT() asm volatile("cp.async.commit_group;\n" ::: "memory")

__device__ __forceinline__ void ldsm4(uint32_t& r0, uint32_t& r1, uint32_t& r2,
                                      uint32_t& r3, uint32_t addr) {
    asm volatile("ldmatrix.sync.aligned.m8n8.x4.shared.b16 {%0,%1,%2,%3}, [%4];"
                 : "=r"(r0), "=r"(r1), "=r"(r2), "=r"(r3) : "r"(addr));
}
__device__ __forceinline__ void ldsm4t(uint32_t& r0, uint32_t& r1, uint32_t& r2,
                                       uint32_t& r3, uint32_t addr) {
    asm volatile("ldmatrix.sync.aligned.m8n8.x4.trans.shared.b16 {%0,%1,%2,%3}, [%4];"
                 : "=r"(r0), "=r"(r1), "=r"(r2), "=r"(r3) : "r"(addr));
}
__device__ __forceinline__ void mma_f16(float* c,
    uint32_t a0, uint32_t a1, uint32_t a2, uint32_t a3, uint32_t b0, uint32_t b1)
{
    asm volatile(
        "mma.sync.aligned.m16n8k16.row.col.f32.f16.f16.f32 "
        "{%0,%1,%2,%3}, {%4,%5,%6,%7}, {%8,%9}, {%0,%1,%2,%3};"
        : "+f"(c[0]), "+f"(c[1]), "+f"(c[2]), "+f"(c[3])
        : "r"(a0), "r"(a1), "r"(a2), "r"(a3), "r"(b0), "r"(b1));
}
__device__ __forceinline__ uint32_t packh2(float a, float b) {
    __half2 h = __floats2half2_rn(a, b);
    return *(uint32_t*)&h;
}

// ---------------- fused weight convert fp32 -> fp16 ----------------
// Block-granular: each 256-thread block owns 1024 contiguous float4s.
// Segment boundaries are 1024-aligned -> resolve segment ONCE per block.
// Each thread converts 4 float4s (stride 256) -> MLP=4.
#define S_WQ 4194304L
#define S_WK 1048576L
#define S_WV 1048576L
#define S_WO 4194304L
#define S_WG 14680064L
#define S_WU 14680064L
#define S_WD 14680064L
#define S_TOTAL (S_WQ + S_WK + S_WV + S_WO + S_WG + S_WU + S_WD)
#define F2H_BLOCKS (S_TOTAL / 1024)   // 53248, exact

__global__ void __launch_bounds__(256) f2h_all_kernel(
    const float4* __restrict__ wq, const float4* __restrict__ wk,
    const float4* __restrict__ wv, const float4* __restrict__ wo,
    const float4* __restrict__ wg, const float4* __restrict__ wu,
    const float4* __restrict__ wd,
    __half2* __restrict__ dqkv, __half2* __restrict__ dwo,
    __half2* __restrict__ dwg, __half2* __restrict__ dwu,
    __half2* __restrict__ dwd)
{
    long j = (long)blockIdx.x * 1024;   // block-base in float4 units
    const float4* src;
    __half2* dst;
    if (j < S_WQ)                      { src = wq; dst = dqkv; }
    else if ((j -= S_WQ) < S_WK)       { src = wk; dst = dqkv + 2 * S_WQ; }
    else if ((j -= S_WK) < S_WV)       { src = wv; dst = dqkv + 2 * (S_WQ + S_WK); }
    else if ((j -= S_WV) < S_WO)       { src = wo; dst = dwo; }
    else if ((j -= S_WO) < S_WG)       { src = wg; dst = dwg; }
    else if ((j -= S_WG) < S_WU)       { src = wu; dst = dwu; }
    else                { j -= S_WU;     src = wd; dst = dwd; }

    const long base = j + threadIdx.x;
    float4 v[4];
#pragma unroll
    for (int r = 0; r < 4; r++) v[r] = src[base + r * 256];
#pragma unroll
    for (int r = 0; r < 4; r++) {
        const long idx = base + r * 256;
        dst[2 * idx]     = __floats2half2_rn(v[r].x, v[r].y);
        dst[2 * idx + 1] = __floats2half2_rn(v[r].z, v[r].w);
    }
}

// ---------------- RMSNorm (fp16 output) ----------------
__global__ void __launch_bounds__(256) rmsnorm_kernel(
    const float* __restrict__ x, const float* __restrict__ w, __half* __restrict__ out)
{
    const int row = blockIdx.x;
    const float4* xv = (const float4*)(x + (size_t)row * H_);
    const float4* wv = (const float4*)w;
    __half2* ov = (__half2*)(out + (size_t)row * H_);

    float4 buf[4];
    float ss = 0.f;
#pragma unroll
    for (int i = 0; i < 4; i++) {
        float4 v = xv[threadIdx.x + i * 256];
        buf[i] = v;
        ss += v.x * v.x + v.y * v.y + v.z * v.z + v.w * v.w;
    }
#pragma unroll
    for (int o = 16; o; o >>= 1) ss += __shfl_xor_sync(0xffffffffu, ss, o);

    __shared__ float wsum[8];
    __shared__ float s_inv;
    if ((threadIdx.x & 31) == 0) wsum[threadIdx.x >> 5] = ss;
    __syncthreads();
    if (threadIdx.x == 0) {
        float tot = 0.f;
#pragma unroll
        for (int i = 0; i < 8; i++) tot += wsum[i];
        s_inv = rsqrtf(tot * (1.f / (float)H_) + 1e-5f);
    }
    __syncthreads();
    const float inv = s_inv;
#pragma unroll
    for (int i = 0; i < 4; i++) {
        float4 v = buf[i];
        float4 ww = wv[threadIdx.x + i * 256];
        ov[(threadIdx.x + i * 256) * 2]     = __floats2half2_rn(v.x * inv * ww.x, v.y * inv * ww.y);
        ov[(threadIdx.x + i * 256) * 2 + 1] = __floats2half2_rn(v.z * inv * ww.z, v.w * inv * ww.w);
    }
}

// ---------------- fused RoPE (q + k): fp32 in, fp16 out, 4 heads/block ----------------
__global__ void __launch_bounds__(256) rope2_kernel(
    const float* __restrict__ qi, const float* __restrict__ ki,
    const int* __restrict__ pos,
    __half* __restrict__ qo, __half* __restrict__ ko)
{
    const int tt = blockIdx.x;
    int h = blockIdx.y * 4 + (threadIdx.x >> 6);   // 0..39
    const int j = threadIdx.x & 63;
    const float p = (float)pos[tt];
    const float invf = expf(-(float)j * 0.20503692777194262f);
    float s, c;
    sincosf(p * invf, &s, &c);
    const float* base;
    __half* ob;
    if (h < HQ_) {
        base = qi + ((size_t)tt * HQ_ + h) * D_ + j;
        ob   = qo + ((size_t)tt * HQ_ + h) * D_ + j;
    } else {
        h -= HQ_;
        base = ki + ((size_t)tt * HKV_ + h) * D_ + j;
        ob   = ko + ((size_t)tt * HKV_ + h) * D_ + j;
    }
    const float x1v = base[0];
    const float x2v = base[64];
    ob[0]  = __float2half(x1v * c - x2v * s);
    ob[64] = __float2half(x2v * c + x1v * s);
}

// ---------------- fp16 tensor-core GEMM: C[M,N] = A[M,K] * B[N,K]^T ----------------
// ROUND-9 CONFIG (empirical optimum): 256 thr, 8 warps 2x4, warp 64x32,
// 3-stage cp.async, single barrier per k-tile, 2 CTAs/SM, grid = (N/128, M/128).
// MODE 0: store  1: C=Cin(f32)+acc  2: C=silu(acc)  3: C=Cin(f16)*acc  4: QKV split
// OUTH: 1 -> fp16 output, 0 -> fp32 output
#define STAGE_A 16384
#define STAGE_BYTES 32768
#define GEMM_SMEM (3 * STAGE_BYTES)

template <int MODE, int OUTH>
__global__ void __launch_bounds__(256, 2) gemm_f16_kernel(
    const __half* __restrict__ A, const __half* __restrict__ B,
    const void* __restrict__ Cin, void* __restrict__ Cv,
    void* __restrict__ Cv2, void* __restrict__ Cv3, int N, int K)
{
    extern __shared__ __align__(1024) char smem[];
    const uint32_t sbase = smem_u32(smem);
    const int tid  = threadIdx.x;
    const int wid  = tid >> 5;
    const int lane = tid & 31;
    const int warpM = (wid >> 2) * 64;
    const int warpN = (wid & 3) * 32;
    const size_t arow0 = (size_t)blockIdx.y * 128;
    const size_t brow0 = (size_t)blockIdx.x * 128;
    const int ntiles = K >> 6;

    const int lrow = tid >> 1;
    const int lch  = (tid & 1) * 4;
    const __half* Ag = A + (arow0 + lrow) * K + lch * 8;
    const __half* Bg = B + (brow0 + lrow) * K + lch * 8;
    uint32_t s_off[4];
#pragma unroll
    for (int i = 0; i < 4; i++) {
        uint32_t o = (uint32_t)(lrow * 128 + (lch + i) * 16);
        s_off[i] = o ^ ((o >> 3) & 0x70);
    }

#define LOADT(t, slot)                                                   \
    {                                                                    \
        const uint32_t sa = sbase + (slot) * STAGE_BYTES;                \
        const __half* ag = Ag + (size_t)(t) * 64;                        \
        const __half* bg = Bg + (size_t)(t) * 64;                        \
        _Pragma("unroll")                                                \
        for (int i = 0; i < 4; i++) {                                    \
            cp_async16(sa + s_off[i], ag + i * 8);                       \
            cp_async16(sa + STAGE_A + s_off[i], bg + i * 8);             \
        }                                                                \
    }

    uint32_t aRow[4], aMask[4], bRow[2], bMask[2];
    const int kbA = (lane >> 4) * 16;
    {
        const int r = lane & 15;
#pragma unroll
        for (int mi = 0; mi < 4; mi++) {
            uint32_t o = (uint32_t)((warpM + mi * 16 + r) * 128);
            aRow[mi]  = o;
            aMask[mi] = (o >> 3) & 0x70;
        }
    }
    const int rn  = (lane & 7) + ((lane >> 4) << 3);
    const int kbB = ((lane >> 3) & 1) * 16;
    {
#pragma unroll
        for (int ni = 0; ni < 2; ni++) {
            uint32_t o = (uint32_t)((warpN + ni * 16 + rn) * 128);
            bRow[ni]  = o;
            bMask[ni] = (o >> 3) & 0x70;
        }
    }

    float acc[4][4][4];
#pragma unroll
    for (int mi = 0; mi < 4; mi++)
#pragma unroll
        for (int nj = 0; nj < 4; nj++)
#pragma unroll
            for (int r = 0; r < 4; r++) acc[mi][nj][r] = 0.f;

    LOADT(0, 0); CP_COMMIT();
    LOADT(1, 1); CP_COMMIT();

    for (int t = 0; t < ntiles; t++) {
        asm volatile("cp.async.wait_group 1;\n" ::: "memory");
        __syncthreads();
        if (t + 2 < ntiles) { LOADT(t + 2, (t + 2) % 3); }
        CP_COMMIT();

        const uint32_t sa = sbase + (t % 3) * STAGE_BYTES;
#pragma unroll
        for (int ks = 0; ks < 4; ks++) {
            uint32_t b[2][4];
#pragma unroll
            for (int ni = 0; ni < 2; ni++)
                ldsm4(b[ni][0], b[ni][1], b[ni][2], b[ni][3],
                      sa + STAGE_A + bRow[ni] + (((uint32_t)(kbB + ks * 32)) ^ bMask[ni]));
#pragma unroll
            for (int mi = 0; mi < 4; mi++) {
                uint32_t a0, a1, a2, a3;
                ldsm4(a0, a1, a2, a3,
                      sa + aRow[mi] + (((uint32_t)(kbA + ks * 32)) ^ aMask[mi]));
#pragma unroll
                for (int nj = 0; nj < 4; nj++)
                    mma_f16(acc[mi][nj], a0, a1, a2, a3,
                            b[nj >> 1][(nj & 1) * 2], b[nj >> 1][(nj & 1) * 2 + 1]);
            }
        }
    }
#undef LOADT

    // epilogue
    const int r0 = (int)arow0 + warpM + (lane >> 2);
    if (MODE == 4) {
        const int gcol0 = blockIdx.x * 128 + warpN + (lane & 3) * 2;
        float* outF = nullptr;
        __half* outH = nullptr;
        int Nout, col0;
        if (gcol0 < 4096)      { outF = (float*)Cv;  Nout = H_;         col0 = gcol0; }
        else if (gcol0 < 5120) { outF = (float*)Cv2; Nout = HKV_ * D_;  col0 = gcol0 - 4096; }
        else                   { outH = (__half*)Cv3; Nout = HKV_ * D_; col0 = gcol0 - 5120; }
#pragma unroll
        for (int mi = 0; mi < 4; mi++) {
#pragma unroll
            for (int h = 0; h < 2; h++) {
                const int row = r0 + mi * 16 + h * 8;
#pragma unroll
                for (int nj = 0; nj < 4; nj++) {
                    const int col = col0 + nj * 8;
                    float vx = acc[mi][nj][h * 2 + 0];
                    float vy = acc[mi][nj][h * 2 + 1];
                    if (outF) {
                        *(float2*)(outF + (size_t)row * Nout + col) = make_float2(vx, vy);
                    } else {
                        *(__half2*)(outH + (size_t)row * Nout + col) = __floats2half2_rn(vx, vy);
                    }
                }
            }
        }
        return;
    }

    const int c0 = blockIdx.x * 128 + warpN + (lane & 3) * 2;
#pragma unroll
    for (int mi = 0; mi < 4; mi++) {
#pragma unroll
        for (int h = 0; h < 2; h++) {
            const int row = r0 + mi * 16 + h * 8;
#pragma unroll
            for (int nj = 0; nj < 4; nj++) {
                const int col = c0 + nj * 8;
                float vx = acc[mi][nj][h * 2 + 0];
                float vy = acc[mi][nj][h * 2 + 1];
                if (MODE == 1) {
                    const float* cin = (const float*)Cin + (size_t)row * N + col;
                    vx += cin[0];
                    vy += cin[1];
                } else if (MODE == 2) {
                    vx = vx / (1.f + expf(-vx));
                    vy = vy / (1.f + expf(-vy));
                } else if (MODE == 3) {
                    const __half2 c2 = *(const __half2*)((const __half*)Cin + (size_t)row * N + col);
                    const float2 cf = __half22float2(c2);
                    vx *= cf.x;
                    vy *= cf.y;
                }
                if (OUTH) {
                    __half2* dst = (__half2*)((__half*)Cv + (size_t)row * N + col);
                    *dst = __floats2half2_rn(vx, vy);
                } else {
                    float2* dst = (float2*)((float*)Cv + (size_t)row * N + col);
                    *dst = make_float2(vx, vy);
                }
            }
        }
    }
}

// ---------------- fp16 tensor-core causal flash attention ----------------
// grid (8, HQ): CTA bx processes q-blocks {bx, 15-bx} -> uniform 32 KV-tiles per CTA.
#define AQ_OFF   0
#define AKV_OFF  32768
#define AKV_STRIDE 32768
#define ATT_SMEM (32768 + 2 * AKV_STRIDE)   // 96KB

__global__ void __launch_bounds__(256) attn16_kernel(
    const __half* __restrict__ qh, const __half* __restrict__ kh,
    const __half* __restrict__ vh, __half* __restrict__ o)
{
    extern __shared__ __align__(1024) char smem[];
    const uint32_t sbase = smem_u32(smem);
    const int tid  = threadIdx.x;
    const int wid  = tid >> 5;
    const int lane = tid & 31;
    const int bx   = blockIdx.x;        // 0..7
    const int head = blockIdx.y;
    const int kvh  = head >> 2;
    const float scale = 0.08838834764831845f;

    const int rA    = lane & 15;
    const int kbA   = (lane >> 4) * 16;
    const int rnB   = (lane & 7) + ((lane >> 4) << 3);
    const int kbB   = ((lane >> 3) & 1) * 16;
    const int rV    = (lane & 7) + ((lane >> 3) & 1) * 8;
    const int dbV   = ((lane >> 4) & 1) * 16;

#define LOADKV(kt, buf)                                                              \
    {                                                                                \
        const int k0l = (kt) * 64;                                                   \
        const uint32_t kb = sbase + AKV_OFF + (buf) * AKV_STRIDE;                    \
        _Pragma("unroll")                                                            \
        for (int i = 0; i < 4; i++) {                                                \
            const int chunk = tid + 256 * i;                                         \
            const int seg = chunk >> 9;                                              \
            const int row = (chunk >> 3) & 63;                                       \
            const int off = chunk & 7;                                               \
            const uint32_t ro = (uint32_t)(row * 128);                               \
            const uint32_t sw = ro + (((uint32_t)(off * 16)) ^ ((ro >> 3) & 0x70));  \
            const size_t gi = (size_t)(k0l + row) * (HKV_ * D_) + kvh * D_           \
                            + seg * 64 + off * 8;                                    \
            cp_async16(kb + seg * 8192 + sw, kh + gi);                               \
            cp_async16(kb + 16384 + seg * 8192 + sw, vh + gi);                       \
        }                                                                            \
    }

#pragma unroll 1
    for (int it = 0; it < 2; it++) {
        const int qblk = (it == 0) ? bx : (15 - bx);
        const int q0   = qblk * 128;
        const int qr0  = q0 + wid * 16;

        // ---- load Q tile ----
#pragma unroll
        for (int i = 0; i < 8; i++) {
            const int chunk = tid + 256 * i;
            const int seg = chunk >> 10;
            const int row = (chunk >> 3) & 127;
            const int off = chunk & 7;
            const uint32_t ro = (uint32_t)(row * 128);
            const uint32_t sw = ro + (((uint32_t)(off * 16)) ^ ((ro >> 3) & 0x70));
            cp_async16(sbase + AQ_OFF + seg * 16384 + sw,
                       qh + (size_t)(q0 + row) * (HQ_ * D_) + head * D_ + seg * 64 + off * 8);
        }
        CP_COMMIT();
        LOADKV(0, 0); CP_COMMIT();

        uint32_t qf[8][4];
        float accO[16][4];
#pragma unroll
        for (int nj = 0; nj < 16; nj++)
#pragma unroll
            for (int r = 0; r < 4; r++) accO[nj][r] = 0.f;
        float m1 = -1e30f, m2 = -1e30f, l1 = 0.f, l2 = 0.f;

        const int ktmax = 2 * qblk + 1;
        for (int kt = 0; kt <= ktmax; kt++) {
            if (kt < ktmax) {
                LOADKV(kt + 1, (kt + 1) & 1);
                CP_COMMIT();
                asm volatile("cp.async.wait_group 1;\n" ::: "memory");
            } else {
                asm volatile("cp.async.wait_group 0;\n" ::: "memory");
            }
            __syncthreads();

            if (kt == 0) {
#pragma unroll
                for (int ks = 0; ks < 8; ks++) {
                    const int seg = ks >> 2;
                    const uint32_t ro = (uint32_t)((wid * 16 + rA) * 128);
                    const uint32_t addr = sbase + AQ_OFF + seg * 16384 + ro
                        + (((uint32_t)(kbA + (ks & 3) * 32)) ^ ((ro >> 3) & 0x70));
                    ldsm4(qf[ks][0], qf[ks][1], qf[ks][2], qf[ks][3], addr);
                }
            }

            const int k0 = kt * 64;
            if (k0 <= qr0 + 15) {
                const uint32_t kbuf = sbase + AKV_OFF + (kt & 1) * AKV_STRIDE;
                float s[8][4];
#pragma unroll
                for (int nj = 0; nj < 8; nj++)
#pragma unroll
                    for (int r = 0; r < 4; r++) s[nj][r] = 0.f;

#pragma unroll
                for (int ks = 0; ks < 8; ks++) {
                    const int seg = ks >> 2;
                    uint32_t b[4][4];
#pragma unroll
                    for (int ni = 0; ni < 4; ni++) {
                        const uint32_t ro = (uint32_t)((ni * 16 + rnB) * 128);
                        ldsm4(b[ni][0], b[ni][1], b[ni][2], b[ni][3],
                              kbuf + seg * 8192 + ro
                              + (((uint32_t)(kbB + (ks & 3) * 32)) ^ ((ro >> 3) & 0x70)));
                    }
#pragma unroll
                    for (int nj = 0; nj < 8; nj++)
                        mma_f16(s[nj], qf[ks][0], qf[ks][1], qf[ks][2], qf[ks][3],
                                b[nj >> 1][(nj & 1) * 2], b[nj >> 1][(nj & 1) * 2 + 1]);
                }

                const int row1 = qr0 + (lane >> 2);
                const int row2 = row1 + 8;
                float rmax1 = -1e30f, rmax2 = -1e30f;
#pragma unroll
                for (int nj = 0; nj < 8; nj++) {
                    const int c0 = k0 + nj * 8 + (lane & 3) * 2;
                    float v0 = s[nj][0] * scale, v1 = s[nj][1] * scale;
                    float v2 = s[nj][2] * scale, v3 = s[nj][3] * scale;
                    if (c0 > row1)     v0 = -1e30f;
                    if (c0 + 1 > row1) v1 = -1e30f;
                    if (c0 > row2)     v2 = -1e30f;
                    if (c0 + 1 > row2) v3 = -1e30f;
                    s[nj][0] = v0; s[nj][1] = v1; s[nj][2] = v2; s[nj][3] = v3;
                    rmax1 = fmaxf(rmax1, fmaxf(v0, v1));
                    rmax2 = fmaxf(rmax2, fmaxf(v2, v3));
                }
#pragma unroll
                for (int off = 1; off <= 2; off <<= 1) {
                    rmax1 = fmaxf(rmax1, __shfl_xor_sync(0xffffffffu, rmax1, off));
                    rmax2 = fmaxf(rmax2, __shfl_xor_sync(0xffffffffu, rmax2, off));
                }
                const float mn1 = fmaxf(m1, rmax1);
                const float mn2 = fmaxf(m2, rmax2);
                const float al1 = expf(m1 - mn1);
                const float al2 = expf(m2 - mn2);
                m1 = mn1; m2 = mn2;

                float ps1 = 0.f, ps2 = 0.f;
#pragma unroll
                for (int nj = 0; nj < 8; nj++) {
                    float p0 = expf(s[nj][0] - mn1);
                    float p1 = expf(s[nj][1] - mn1);
                    float p2 = expf(s[nj][2] - mn2);
                    float p3 = expf(s[nj][3] - mn2);
                    s[nj][0] = p0; s[nj][1] = p1; s[nj][2] = p2; s[nj][3] = p3;
                    ps1 += p0 + p1;
                    ps2 += p2 + p3;
                }
#pragma unroll
                for (int off = 1; off <= 2; off <<= 1) {
                    ps1 += __shfl_xor_sync(0xffffffffu, ps1, off);
                    ps2 += __shfl_xor_sync(0xffffffffu, ps2, off);
                }
                l1 = l1 * al1 + ps1;
                l2 = l2 * al2 + ps2;
#pragma unroll
                for (int nj = 0; nj < 16; nj++) {
                    accO[nj][0] *= al1; accO[nj][1] *= al1;
                    accO[nj][2] *= al2; accO[nj][3] *= al2;
                }

                const uint32_t vbuf = kbuf + 16384;
#pragma unroll
                for (int kv = 0; kv < 4; kv++) {
                    const uint32_t a0 = packh2(s[2 * kv][0],     s[2 * kv][1]);
                    const uint32_t a1 = packh2(s[2 * kv][2],     s[2 * kv][3]);
                    const uint32_t a2 = packh2(s[2 * kv + 1][0], s[2 * kv + 1][1]);
                    const uint32_t a3 = packh2(s[2 * kv + 1][2], s[2 * kv + 1][3]);
#pragma unroll
                    for (int p = 0; p < 8; p++) {
                        const int seg = p >> 2;
                        const uint32_t ro = (uint32_t)((kv * 16 + rV) * 128);
                        uint32_t b0, b1, b2, b3;
                        ldsm4t(b0, b1, b2, b3,
                               vbuf + seg * 8192 + ro
                               + (((uint32_t)((p & 3) * 32 + dbV)) ^ ((ro >> 3) & 0x70)));
                        mma_f16(accO[2 * p],     a0, a1, a2, a3, b0, b1);
                        mma_f16(accO[2 * p + 1], a0, a1, a2, a3, b2, b3);
                    }
                }
            }
            __syncthreads();
        }

        // ---- epilogue for this q-block ----
        const float inv1 = 1.f / l1;
        const float inv2 = 1.f / l2;
        const int row1 = qr0 + (lane >> 2);
        const int colb = head * D_ + (lane & 3) * 2;
#pragma unroll
        for (int nj = 0; nj < 16; nj++) {
            __half2* d1 = (__half2*)(o + (size_t)row1 * H_ + colb + nj * 8);
            __half2* d2 = (__half2*)(o + (size_t)(row1 + 8) * H_ + colb + nj * 8);
            *d1 = __floats2half2_rn(accO[nj][0] * inv1, accO[nj][1] * inv1);
            *d2 = __floats2half2_rn(accO[nj][2] * inv2, accO[nj][3] * inv2);
        }
    }
#undef LOADKV
}

// ---------------- launch ----------------
extern "C" void kernel_launch(void* const* d_in, const int* in_sizes, int n_in,
                              void* d_out, int out_size)
{
    (void)in_sizes; (void)n_in; (void)out_size;
    const float* x      = (const float*)d_in[0];
    const int*   pos    = (const int*)  d_in[1];
    const float* w_q    = (const float*)d_in[2];
    const float* w_k    = (const float*)d_in[3];
    const float* w_v    = (const float*)d_in[4];
    const float* w_o    = (const float*)d_in[5];
    const float* w_gate = (const float*)d_in[6];
    const float* w_up   = (const float*)d_in[7];
    const float* w_down = (const float*)d_in[8];
    const float* rms1   = (const float*)d_in[9];
    const float* rms2   = (const float*)d_in[10];
    float* out = (float*)d_out;

    __half *h, *attn, *gu, *qh, *kh, *vh, *gate, *wqkv, *wo, *wg, *wu, *wd;
    float *q, *k, *x1;
    cudaGetSymbolAddress((void**)&h,    g_h);
    cudaGetSymbolAddress((void**)&q,    g_q);
    cudaGetSymbolAddress((void**)&k,    g_k);
    cudaGetSymbolAddress((void**)&qh,   g_qh);
    cudaGetSymbolAddress((void**)&kh,   g_kh);
    cudaGetSymbolAddress((void**)&vh,   g_vh);
    cudaGetSymbolAddress((void**)&attn, g_attn);
    cudaGetSymbolAddress((void**)&x1,   g_x1);
    cudaGetSymbolAddress((void**)&gate, g_gate);
    cudaGetSymbolAddress((void**)&gu,   g_gu);
    cudaGetSymbolAddress((void**)&wqkv, g_wqkv);
    cudaGetSymbolAddress((void**)&wo,   g_wo);
    cudaGetSymbolAddress((void**)&wg,   g_wg);
    cudaGetSymbolAddress((void**)&wu,   g_wu);
    cudaGetSymbolAddress((void**)&wd,   g_wd);

    cudaFuncSetAttribute(attn16_kernel, cudaFuncAttributeMaxDynamicSharedMemorySize, ATT_SMEM);
    cudaFuncSetAttribute(gemm_f16_kernel<1,0>, cudaFuncAttributeMaxDynamicSharedMemorySize, GEMM_SMEM);
    cudaFuncSetAttribute(gemm_f16_kernel<2,1>, cudaFuncAttributeMaxDynamicSharedMemorySize, GEMM_SMEM);
    cudaFuncSetAttribute(gemm_f16_kernel<3,1>, cudaFuncAttributeMaxDynamicSharedMemorySize, GEMM_SMEM);
    cudaFuncSetAttribute(gemm_f16_kernel<4,0>, cudaFuncAttributeMaxDynamicSharedMemorySize, GEMM_SMEM);

    // 0. ALL weights -> fp16 in ONE launch (block-granular segments, MLP=4)
    f2h_all_kernel<<<(unsigned)F2H_BLOCKS, 256>>>(
        (const float4*)w_q, (const float4*)w_k, (const float4*)w_v,
        (const float4*)w_o, (const float4*)w_gate, (const float4*)w_up,
        (const float4*)w_down,
        (__half2*)wqkv, (__half2*)wo, (__half2*)wg, (__half2*)wu, (__half2*)wd);

    // 1. h = rmsnorm(x) * rms1  (fp16)
    rmsnorm_kernel<<<T_, 256>>>(x, rms1, h);
    // 2. fused QKV projection (q fp32, k fp32, v fp16), N=6144
    gemm_f16_kernel<4,0><<<dim3(48, T_ / 128), 256, GEMM_SMEM>>>(h, wqkv, nullptr, q, k, vh, 0, H_);
    // 3. fused RoPE (fp32 -> fp16), 4 heads per block
    rope2_kernel<<<dim3(T_, (HQ_ + HKV_) / 4), 256>>>(q, k, pos, qh, kh);
    // 4. causal attention (fp16 tensor cores, balanced)
    attn16_kernel<<<dim3(8, HQ_), 256, ATT_SMEM>>>(qh, kh, vh, attn);
    // 5. x1 = x + attn @ w_o^T
    gemm_f16_kernel<1,0><<<dim3(H_ / 128, T_ / 128), 256, GEMM_SMEM>>>(attn, wo, x, x1, nullptr, nullptr, H_, H_);
    // 6. h = rmsnorm(x1) * rms2 (fp16)
    rmsnorm_kernel<<<T_, 256>>>(x1, rms2, h);
    // 7. gate = silu(h @ w_gate^T)  (fp16)
    gemm_f16_kernel<2,1><<<dim3(I_ / 128, T_ / 128), 256, GEMM_SMEM>>>(h, wg, nullptr, gate, nullptr, nullptr, I_, H_);
    // 8. gu = gate * (h @ w_up^T)  (fp16)
    gemm_f16_kernel<3,1><<<dim3(I_ / 128, T_ / 128), 256, GEMM_SMEM>>>(h, wu, gate, gu, nullptr, nullptr, I_, H_);
    // 9. out = x1 + gu @ w_down^T
    gemm_f16_kernel<1,0><<<dim3(H_ / 128, T_ / 128), 256, GEMM_SMEM>>>(gu, wd, x1, out, nullptr, nullptr, H_, I_);
}

// round 16
// speedup vs baseline: 1.6072x; 1.0462x over previous
#include <cuda_runtime.h>
#include <cuda_fp16.h>
#include <cstddef>
#include <cstdint>
#include <math.h>

// ---------------- problem constants ----------------
#define T_  2048
#define H_  4096
#define HQ_ 32
#define HKV_ 8
#define D_  128
#define I_  14336

// ---------------- scratch (device globals; no allocation allowed) ----------------
// LAYOUT FROZEN (order & sizes identical to round 12/14/15)
__device__ __half g_h   [T_ * H_];            // rmsnorm out (fp16)
__device__ float  g_q   [T_ * HQ_ * D_];      // q proj fp32 (pre-rope)
__device__ float  g_k   [T_ * HKV_ * D_];     // k proj fp32 (pre-rope)
__device__ __half g_qh  [T_ * HQ_ * D_];      // q fp16 post-rope
__device__ __half g_kh  [T_ * HKV_ * D_];     // k fp16 post-rope
__device__ __half g_vh  [T_ * HKV_ * D_];     // v fp16
__device__ __half g_attn[T_ * H_];            // attention out (fp16)
__device__ float  g_x1  [T_ * H_];
__device__ __half g_gate[T_ * (size_t)I_];
__device__ __half g_gu  [T_ * (size_t)I_];
__device__ __half g_wqkv[(size_t)(H_ + 2 * HKV_ * D_) * H_];
__device__ __half g_wo[(size_t)H_ * H_];
__device__ __half g_wg[(size_t)I_ * H_];
__device__ __half g_wu[(size_t)I_ * H_];
__device__ __half g_wd[(size_t)H_ * I_];

// ---------------- helpers ----------------
__device__ __forceinline__ uint32_t smem_u32(const void* p) {
    return (uint32_t)__cvta_generic_to_shared(p);
}
__device__ __forceinline__ void cp_async16(uint32_t saddr, const void* gmem) {
    asm volatile("cp.async.cg.shared.global [%0], [%1], 16;\n" :: "r"(saddr), "l"(gmem));
}
#define CP_COMMIT() asm volatile("cp.async.commit_group;\n" ::: "memory")

__device__ __forceinline__ void ldsm4(uint32_t& r0, uint32_t& r1, uint32_t& r2,
                                      uint32_t& r3, uint32_t addr) {
    asm volatile("ldmatrix.sync.aligned.m8n8.x4.shared.b16 {%0,%1,%2,%3}, [%4];"
                 : "=r"(r0), "=r"(r1), "=r"(r2), "=r"(r3) : "r"(addr));
}
__device__ __forceinline__ void ldsm4t(uint32_t& r0, uint32_t& r1, uint32_t& r2,
                                       uint32_t& r3, uint32_t addr) {
    asm volatile("ldmatrix.sync.aligned.m8n8.x4.trans.shared.b16 {%0,%1,%2,%3}, [%4];"
                 : "=r"(r0), "=r"(r1), "=r"(r2), "=r"(r3) : "r"(addr));
}
__device__ __forceinline__ void mma_f16(float* c,
    uint32_t a0, uint32_t a1, uint32_t a2, uint32_t a3, uint32_t b0, uint32_t b1)
{
    asm volatile(
        "mma.sync.aligned.m16n8k16.row.col.f32.f16.f16.f32 "
        "{%0,%1,%2,%3}, {%4,%5,%6,%7}, {%8,%9}, {%0,%1,%2,%3};"
        : "+f"(c[0]), "+f"(c[1]), "+f"(c[2]), "+f"(c[3])
        : "r"(a0), "r"(a1), "r"(a2), "r"(a3), "r"(b0), "r"(b1));
}
__device__ __forceinline__ uint32_t packh2(float a, float b) {
    __half2 h = __floats2half2_rn(a, b);
    return *(uint32_t*)&h;
}

// ---------------- fused weight convert fp32 -> fp16 ----------------
// Block-granular: each 256-thread block owns 2048 contiguous float4s
// (all segment boundaries divide 2048). Each thread converts 8 float4s -> MLP=8.
#define S_WQ 4194304L
#define S_WK 1048576L
#define S_WV 1048576L
#define S_WO 4194304L
#define S_WG 14680064L
#define S_WU 14680064L
#define S_WD 14680064L
#define S_TOTAL (S_WQ + S_WK + S_WV + S_WO + S_WG + S_WU + S_WD)
#define F2H_BLOCKS (S_TOTAL / 2048)   // 26624, exact

__global__ void __launch_bounds__(256) f2h_all_kernel(
    const float4* __restrict__ wq, const float4* __restrict__ wk,
    const float4* __restrict__ wv, const float4* __restrict__ wo,
    const float4* __restrict__ wg, const float4* __restrict__ wu,
    const float4* __restrict__ wd,
    __half2* __restrict__ dqkv, __half2* __restrict__ dwo,
    __half2* __restrict__ dwg, __half2* __restrict__ dwu,
    __half2* __restrict__ dwd)
{
    long j = (long)blockIdx.x * 2048;   // block-base in float4 units
    const float4* src;
    __half2* dst;
    if (j < S_WQ)                      { src = wq; dst = dqkv; }
    else if ((j -= S_WQ) < S_WK)       { src = wk; dst = dqkv + 2 * S_WQ; }
    else if ((j -= S_WK) < S_WV)       { src = wv; dst = dqkv + 2 * (S_WQ + S_WK); }
    else if ((j -= S_WV) < S_WO)       { src = wo; dst = dwo; }
    else if ((j -= S_WO) < S_WG)       { src = wg; dst = dwg; }
    else if ((j -= S_WG) < S_WU)       { src = wu; dst = dwu; }
    else                { j -= S_WU;     src = wd; dst = dwd; }

    const long base = j + threadIdx.x;
    float4 v[8];
#pragma unroll
    for (int r = 0; r < 8; r++) v[r] = src[base + r * 256];
#pragma unroll
    for (int r = 0; r < 8; r++) {
        const long idx = base + r * 256;
        dst[2 * idx]     = __floats2half2_rn(v[r].x, v[r].y);
        dst[2 * idx + 1] = __floats2half2_rn(v[r].z, v[r].w);
    }
}

// ---------------- RMSNorm (fp16 output) ----------------
__global__ void __launch_bounds__(256) rmsnorm_kernel(
    const float* __restrict__ x, const float* __restrict__ w, __half* __restrict__ out)
{
    const int row = blockIdx.x;
    const float4* xv = (const float4*)(x + (size_t)row * H_);
    const float4* wv = (const float4*)w;
    __half2* ov = (__half2*)(out + (size_t)row * H_);

    float4 buf[4];
    float ss = 0.f;
#pragma unroll
    for (int i = 0; i < 4; i++) {
        float4 v = xv[threadIdx.x + i * 256];
        buf[i] = v;
        ss += v.x * v.x + v.y * v.y + v.z * v.z + v.w * v.w;
    }
#pragma unroll
    for (int o = 16; o; o >>= 1) ss += __shfl_xor_sync(0xffffffffu, ss, o);

    __shared__ float wsum[8];
    __shared__ float s_inv;
    if ((threadIdx.x & 31) == 0) wsum[threadIdx.x >> 5] = ss;
    __syncthreads();
    if (threadIdx.x == 0) {
        float tot = 0.f;
#pragma unroll
        for (int i = 0; i < 8; i++) tot += wsum[i];
        s_inv = rsqrtf(tot * (1.f / (float)H_) + 1e-5f);
    }
    __syncthreads();
    const float inv = s_inv;
#pragma unroll
    for (int i = 0; i < 4; i++) {
        float4 v = buf[i];
        float4 ww = wv[threadIdx.x + i * 256];
        ov[(threadIdx.x + i * 256) * 2]     = __floats2half2_rn(v.x * inv * ww.x, v.y * inv * ww.y);
        ov[(threadIdx.x + i * 256) * 2 + 1] = __floats2half2_rn(v.z * inv * ww.z, v.w * inv * ww.w);
    }
}

// ---------------- fused RoPE (q + k): fp32 in, fp16 out, 4 heads/block ----------------
__global__ void __launch_bounds__(256) rope2_kernel(
    const float* __restrict__ qi, const float* __restrict__ ki,
    const int* __restrict__ pos,
    __half* __restrict__ qo, __half* __restrict__ ko)
{
    const int tt = blockIdx.x;
    int h = blockIdx.y * 4 + (threadIdx.x >> 6);   // 0..39
    const int j = threadIdx.x & 63;
    const float p = (float)pos[tt];
    const float invf = expf(-(float)j * 0.20503692777194262f);
    float s, c;
    sincosf(p * invf, &s, &c);
    const float* base;
    __half* ob;
    if (h < HQ_) {
        base = qi + ((size_t)tt * HQ_ + h) * D_ + j;
        ob   = qo + ((size_t)tt * HQ_ + h) * D_ + j;
    } else {
        h -= HQ_;
        base = ki + ((size_t)tt * HKV_ + h) * D_ + j;
        ob   = ko + ((size_t)tt * HKV_ + h) * D_ + j;
    }
    const float x1v = base[0];
    const float x2v = base[64];
    ob[0]  = __float2half(x1v * c - x2v * s);
    ob[64] = __float2half(x2v * c + x1v * s);
}

// ---------------- fp16 tensor-core GEMM: C[M,N] = A[M,K] * B[N,K]^T ----------------
// ROUND-9 macro-config; inner loop hoists all 6 ldsm per ks before the MMA burst.
// MODE 0: store  1: C=Cin(f32)+acc  2: C=silu(acc)  3: C=Cin(f16)*acc  4: QKV split
// OUTH: 1 -> fp16 output, 0 -> fp32 output
#define STAGE_A 16384
#define STAGE_BYTES 32768
#define GEMM_SMEM (3 * STAGE_BYTES)

template <int MODE, int OUTH>
__global__ void __launch_bounds__(256, 2) gemm_f16_kernel(
    const __half* __restrict__ A, const __half* __restrict__ B,
    const void* __restrict__ Cin, void* __restrict__ Cv,
    void* __restrict__ Cv2, void* __restrict__ Cv3, int N, int K)
{
    extern __shared__ __align__(1024) char smem[];
    const uint32_t sbase = smem_u32(smem);
    const int tid  = threadIdx.x;
    const int wid  = tid >> 5;
    const int lane = tid & 31;
    const int warpM = (wid >> 2) * 64;
    const int warpN = (wid & 3) * 32;
    const size_t arow0 = (size_t)blockIdx.y * 128;
    const size_t brow0 = (size_t)blockIdx.x * 128;
    const int ntiles = K >> 6;

    const int lrow = tid >> 1;
    const int lch  = (tid & 1) * 4;
    const __half* Ag = A + (arow0 + lrow) * K + lch * 8;
    const __half* Bg = B + (brow0 + lrow) * K + lch * 8;
    uint32_t s_off[4];
#pragma unroll
    for (int i = 0; i < 4; i++) {
        uint32_t o = (uint32_t)(lrow * 128 + (lch + i) * 16);
        s_off[i] = o ^ ((o >> 3) & 0x70);
    }

#define LOADT(t, slot)                                                   \
    {                                                                    \
        const uint32_t sa = sbase + (slot) * STAGE_BYTES;                \
        const __half* ag = Ag + (size_t)(t) * 64;                        \
        const __half* bg = Bg + (size_t)(t) * 64;                        \
        _Pragma("unroll")                                                \
        for (int i = 0; i < 4; i++) {                                    \
            cp_async16(sa + s_off[i], ag + i * 8);                       \
            cp_async16(sa + STAGE_A + s_off[i], bg + i * 8);             \
        }                                                                \
    }

    uint32_t aRow[4], aMask[4], bRow[2], bMask[2];
    const int kbA = (lane >> 4) * 16;
    {
        const int r = lane & 15;
#pragma unroll
        for (int mi = 0; mi < 4; mi++) {
            uint32_t o = (uint32_t)((warpM + mi * 16 + r) * 128);
            aRow[mi]  = o;
            aMask[mi] = (o >> 3) & 0x70;
        }
    }
    const int rn  = (lane & 7) + ((lane >> 4) << 3);
    const int kbB = ((lane >> 3) & 1) * 16;
    {
#pragma unroll
        for (int ni = 0; ni < 2; ni++) {
            uint32_t o = (uint32_t)((warpN + ni * 16 + rn) * 128);
            bRow[ni]  = o;
            bMask[ni] = (o >> 3) & 0x70;
        }
    }

    float acc[4][4][4];
#pragma unroll
    for (int mi = 0; mi < 4; mi++)
#pragma unroll
        for (int nj = 0; nj < 4; nj++)
#pragma unroll
            for (int r = 0; r < 4; r++) acc[mi][nj][r] = 0.f;

    LOADT(0, 0); CP_COMMIT();
    LOADT(1, 1); CP_COMMIT();

    for (int t = 0; t < ntiles; t++) {
        asm volatile("cp.async.wait_group 1;\n" ::: "memory");
        __syncthreads();
        if (t + 2 < ntiles) { LOADT(t + 2, (t + 2) % 3); }
        CP_COMMIT();

        const uint32_t sa = sbase + (t % 3) * STAGE_BYTES;
#pragma unroll
        for (int ks = 0; ks < 4; ks++) {
            // hoist ALL fragment loads for this ks, then a clean MMA burst
            uint32_t b[2][4];
            uint32_t a[4][4];
#pragma unroll
            for (int ni = 0; ni < 2; ni++)
                ldsm4(b[ni][0], b[ni][1], b[ni][2], b[ni][3],
                      sa + STAGE_A + bRow[ni] + (((uint32_t)(kbB + ks * 32)) ^ bMask[ni]));
#pragma unroll
            for (int mi = 0; mi < 4; mi++)
                ldsm4(a[mi][0], a[mi][1], a[mi][2], a[mi][3],
                      sa + aRow[mi] + (((uint32_t)(kbA + ks * 32)) ^ aMask[mi]));
#pragma unroll
            for (int mi = 0; mi < 4; mi++)
#pragma unroll
                for (int nj = 0; nj < 4; nj++)
                    mma_f16(acc[mi][nj], a[mi][0], a[mi][1], a[mi][2], a[mi][3],
                            b[nj >> 1][(nj & 1) * 2], b[nj >> 1][(nj & 1) * 2 + 1]);
        }
    }
#undef LOADT

    // epilogue
    const int r0 = (int)arow0 + warpM + (lane >> 2);
    if (MODE == 4) {
        const int gcol0 = blockIdx.x * 128 + warpN + (lane & 3) * 2;
        float* outF = nullptr;
        __half* outH = nullptr;
        int Nout, col0;
        if (gcol0 < 4096)      { outF = (float*)Cv;  Nout = H_;         col0 = gcol0; }
        else if (gcol0 < 5120) { outF = (float*)Cv2; Nout = HKV_ * D_;  col0 = gcol0 - 4096; }
        else                   { outH = (__half*)Cv3; Nout = HKV_ * D_; col0 = gcol0 - 5120; }
#pragma unroll
        for (int mi = 0; mi < 4; mi++) {
#pragma unroll
            for (int h = 0; h < 2; h++) {
                const int row = r0 + mi * 16 + h * 8;
#pragma unroll
                for (int nj = 0; nj < 4; nj++) {
                    const int col = col0 + nj * 8;
                    float vx = acc[mi][nj][h * 2 + 0];
                    float vy = acc[mi][nj][h * 2 + 1];
                    if (outF) {
                        *(float2*)(outF + (size_t)row * Nout + col) = make_float2(vx, vy);
                    } else {
                        *(__half2*)(outH + (size_t)row * Nout + col) = __floats2half2_rn(vx, vy);
                    }
                }
            }
        }
        return;
    }

    const int c0 = blockIdx.x * 128 + warpN + (lane & 3) * 2;
#pragma unroll
    for (int mi = 0; mi < 4; mi++) {
#pragma unroll
        for (int h = 0; h < 2; h++) {
            const int row = r0 + mi * 16 + h * 8;
#pragma unroll
            for (int nj = 0; nj < 4; nj++) {
                const int col = c0 + nj * 8;
                float vx = acc[mi][nj][h * 2 + 0];
                float vy = acc[mi][nj][h * 2 + 1];
                if (MODE == 1) {
                    const float* cin = (const float*)Cin + (size_t)row * N + col;
                    vx += cin[0];
                    vy += cin[1];
                } else if (MODE == 2) {
                    vx = vx / (1.f + expf(-vx));
                    vy = vy / (1.f + expf(-vy));
                } else if (MODE == 3) {
                    const __half2 c2 = *(const __half2*)((const __half*)Cin + (size_t)row * N + col);
                    const float2 cf = __half22float2(c2);
                    vx *= cf.x;
                    vy *= cf.y;
                }
                if (OUTH) {
                    __half2* dst = (__half2*)((__half*)Cv + (size_t)row * N + col);
                    *dst = __floats2half2_rn(vx, vy);
                } else {
                    float2* dst = (float2*)((float*)Cv + (size_t)row * N + col);
                    *dst = make_float2(vx, vy);
                }
            }
        }
    }
}

// ---------------- fp16 tensor-core causal flash attention ----------------
// grid (8, HQ): CTA bx processes q-blocks {bx, 15-bx} -> uniform 32 KV-tiles per CTA.
#define AQ_OFF   0
#define AKV_OFF  32768
#define AKV_STRIDE 32768
#define ATT_SMEM (32768 + 2 * AKV_STRIDE)   // 96KB

__global__ void __launch_bounds__(256) attn16_kernel(
    const __half* __restrict__ qh, const __half* __restrict__ kh,
    const __half* __restrict__ vh, __half* __restrict__ o)
{
    extern __shared__ __align__(1024) char smem[];
    const uint32_t sbase = smem_u32(smem);
    const int tid  = threadIdx.x;
    const int wid  = tid >> 5;
    const int lane = tid & 31;
    const int bx   = blockIdx.x;        // 0..7
    const int head = blockIdx.y;
    const int kvh  = head >> 2;
    const float scale = 0.08838834764831845f;

    const int rA    = lane & 15;
    const int kbA   = (lane >> 4) * 16;
    const int rnB   = (lane & 7) + ((lane >> 4) << 3);
    const int kbB   = ((lane >> 3) & 1) * 16;
    const int rV    = (lane & 7) + ((lane >> 3) & 1) * 8;
    const int dbV   = ((lane >> 4) & 1) * 16;

#define LOADKV(kt, buf)                                                              \
    {                                                                                \
        const int k0l = (kt) * 64;                                                   \
        const uint32_t kb = sbase + AKV_OFF + (buf) * AKV_STRIDE;                    \
        _Pragma("unroll")                                                            \
        for (int i = 0; i < 4; i++) {                                                \
            const int chunk = tid + 256 * i;                                         \
            const int seg = chunk >> 9;                                              \
            const int row = (chunk >> 3) & 63;                                       \
            const int off = chunk & 7;                                               \
            const uint32_t ro = (uint32_t)(row * 128);                               \
            const uint32_t sw = ro + (((uint32_t)(off * 16)) ^ ((ro >> 3) & 0x70));  \
            const size_t gi = (size_t)(k0l + row) * (HKV_ * D_) + kvh * D_           \
                            + seg * 64 + off * 8;                                    \
            cp_async16(kb + seg * 8192 + sw, kh + gi);                               \
            cp_async16(kb + 16384 + seg * 8192 + sw, vh + gi);                       \
        }                                                                            \
    }

#pragma unroll 1
    for (int it = 0; it < 2; it++) {
        const int qblk = (it == 0) ? bx : (15 - bx);
        const int q0   = qblk * 128;
        const int qr0  = q0 + wid * 16;

        // ---- load Q tile ----
#pragma unroll
        for (int i = 0; i < 8; i++) {
            const int chunk = tid + 256 * i;
            const int seg = chunk >> 10;
            const int row = (chunk >> 3) & 127;
            const int off = chunk & 7;
            const uint32_t ro = (uint32_t)(row * 128);
            const uint32_t sw = ro + (((uint32_t)(off * 16)) ^ ((ro >> 3) & 0x70));
            cp_async16(sbase + AQ_OFF + seg * 16384 + sw,
                       qh + (size_t)(q0 + row) * (HQ_ * D_) + head * D_ + seg * 64 + off * 8);
        }
        CP_COMMIT();
        LOADKV(0, 0); CP_COMMIT();

        uint32_t qf[8][4];
        float accO[16][4];
#pragma unroll
        for (int nj = 0; nj < 16; nj++)
#pragma unroll
            for (int r = 0; r < 4; r++) accO[nj][r] = 0.f;
        float m1 = -1e30f, m2 = -1e30f, l1 = 0.f, l2 = 0.f;

        const int ktmax = 2 * qblk + 1;
        for (int kt = 0; kt <= ktmax; kt++) {
            if (kt < ktmax) {
                LOADKV(kt + 1, (kt + 1) & 1);
                CP_COMMIT();
                asm volatile("cp.async.wait_group 1;\n" ::: "memory");
            } else {
                asm volatile("cp.async.wait_group 0;\n" ::: "memory");
            }
            __syncthreads();

            if (kt == 0) {
#pragma unroll
                for (int ks = 0; ks < 8; ks++) {
                    const int seg = ks >> 2;
                    const uint32_t ro = (uint32_t)((wid * 16 + rA) * 128);
                    const uint32_t addr = sbase + AQ_OFF + seg * 16384 + ro
                        + (((uint32_t)(kbA + (ks & 3) * 32)) ^ ((ro >> 3) & 0x70));
                    ldsm4(qf[ks][0], qf[ks][1], qf[ks][2], qf[ks][3], addr);
                }
            }

            const int k0 = kt * 64;
            if (k0 <= qr0 + 15) {
                const uint32_t kbuf = sbase + AKV_OFF + (kt & 1) * AKV_STRIDE;
                float s[8][4];
#pragma unroll
                for (int nj = 0; nj < 8; nj++)
#pragma unroll
                    for (int r = 0; r < 4; r++) s[nj][r] = 0.f;

#pragma unroll
                for (int ks = 0; ks < 8; ks++) {
                    const int seg = ks >> 2;
                    uint32_t b[4][4];
#pragma unroll
                    for (int ni = 0; ni < 4; ni++) {
                        const uint32_t ro = (uint32_t)((ni * 16 + rnB) * 128);
                        ldsm4(b[ni][0], b[ni][1], b[ni][2], b[ni][3],
                              kbuf + seg * 8192 + ro
                              + (((uint32_t)(kbB + (ks & 3) * 32)) ^ ((ro >> 3) & 0x70)));
                    }
#pragma unroll
                    for (int nj = 0; nj < 8; nj++)
                        mma_f16(s[nj], qf[ks][0], qf[ks][1], qf[ks][2], qf[ks][3],
                                b[nj >> 1][(nj & 1) * 2], b[nj >> 1][(nj & 1) * 2 + 1]);
                }

                const int row1 = qr0 + (lane >> 2);
                const int row2 = row1 + 8;
                float rmax1 = -1e30f, rmax2 = -1e30f;
#pragma unroll
                for (int nj = 0; nj < 8; nj++) {
                    const int c0 = k0 + nj * 8 + (lane & 3) * 2;
                    float v0 = s[nj][0] * scale, v1 = s[nj][1] * scale;
                    float v2 = s[nj][2] * scale, v3 = s[nj][3] * scale;
                    if (c0 > row1)     v0 = -1e30f;
                    if (c0 + 1 > row1) v1 = -1e30f;
                    if (c0 > row2)     v2 = -1e30f;
                    if (c0 + 1 > row2) v3 = -1e30f;
                    s[nj][0] = v0; s[nj][1] = v1; s[nj][2] = v2; s[nj][3] = v3;
                    rmax1 = fmaxf(rmax1, fmaxf(v0, v1));
                    rmax2 = fmaxf(rmax2, fmaxf(v2, v3));
                }
#pragma unroll
                for (int off = 1; off <= 2; off <<= 1) {
                    rmax1 = fmaxf(rmax1, __shfl_xor_sync(0xffffffffu, rmax1, off));
                    rmax2 = fmaxf(rmax2, __shfl_xor_sync(0xffffffffu, rmax2, off));
                }
                const float mn1 = fmaxf(m1, rmax1);
                const float mn2 = fmaxf(m2, rmax2);
                const float al1 = expf(m1 - mn1);
                const float al2 = expf(m2 - mn2);
                m1 = mn1; m2 = mn2;

                float ps1 = 0.f, ps2 = 0.f;
#pragma unroll
                for (int nj = 0; nj < 8; nj++) {
                    float p0 = expf(s[nj][0] - mn1);
                    float p1 = expf(s[nj][1] - mn1);
                    float p2 = expf(s[nj][2] - mn2);
                    float p3 = expf(s[nj][3] - mn2);
                    s[nj][0] = p0; s[nj][1] = p1; s[nj][2] = p2; s[nj][3] = p3;
                    ps1 += p0 + p1;
                    ps2 += p2 + p3;
                }
#pragma unroll
                for (int off = 1; off <= 2; off <<= 1) {
                    ps1 += __shfl_xor_sync(0xffffffffu, ps1, off);
                    ps2 += __shfl_xor_sync(0xffffffffu, ps2, off);
                }
                l1 = l1 * al1 + ps1;
                l2 = l2 * al2 + ps2;
#pragma unroll
                for (int nj = 0; nj < 16; nj++) {
                    accO[nj][0] *= al1; accO[nj][1] *= al1;
                    accO[nj][2] *= al2; accO[nj][3] *= al2;
                }

                const uint32_t vbuf = kbuf + 16384;
#pragma unroll
                for (int kv = 0; kv < 4; kv++) {
                    const uint32_t a0 = packh2(s[2 * kv][0],     s[2 * kv][1]);
                    const uint32_t a1 = packh2(s[2 * kv][2],     s[2 * kv][3]);
                    const uint32_t a2 = packh2(s[2 * kv + 1][0], s[2 * kv + 1][1]);
                    const uint32_t a3 = packh2(s[2 * kv + 1][2], s[2 * kv + 1][3]);
#pragma unroll
                    for (int p = 0; p < 8; p++) {
                        const int seg = p >> 2;
                        const uint32_t ro = (uint32_t)((kv * 16 + rV) * 128);
                        uint32_t b0, b1, b2, b3;
                        ldsm4t(b0, b1, b2, b3,
                               vbuf + seg * 8192 + ro
                               + (((uint32_t)((p & 3) * 32 + dbV)) ^ ((ro >> 3) & 0x70)));
                        mma_f16(accO[2 * p],     a0, a1, a2, a3, b0, b1);
                        mma_f16(accO[2 * p + 1], a0, a1, a2, a3, b2, b3);
                    }
                }
            }
            __syncthreads();
        }

        // ---- epilogue for this q-block ----
        const float inv1 = 1.f / l1;
        const float inv2 = 1.f / l2;
        const int row1 = qr0 + (lane >> 2);
        const int colb = head * D_ + (lane & 3) * 2;
#pragma unroll
        for (int nj = 0; nj < 16; nj++) {
            __half2* d1 = (__half2*)(o + (size_t)row1 * H_ + colb + nj * 8);
            __half2* d2 = (__half2*)(o + (size_t)(row1 + 8) * H_ + colb + nj * 8);
            *d1 = __floats2half2_rn(accO[nj][0] * inv1, accO[nj][1] * inv1);
            *d2 = __floats2half2_rn(accO[nj][2] * inv2, accO[nj][3] * inv2);
        }
    }
#undef LOADKV
}

// ---------------- launch ----------------
extern "C" void kernel_launch(void* const* d_in, const int* in_sizes, int n_in,
                              void* d_out, int out_size)
{
    (void)in_sizes; (void)n_in; (void)out_size;
    const float* x      = (const float*)d_in[0];
    const int*   pos    = (const int*)  d_in[1];
    const float* w_q    = (const float*)d_in[2];
    const float* w_k    = (const float*)d_in[3];
    const float* w_v    = (const float*)d_in[4];
    const float* w_o    = (const float*)d_in[5];
    const float* w_gate = (const float*)d_in[6];
    const float* w_up   = (const float*)d_in[7];
    const float* w_down = (const float*)d_in[8];
    const float* rms1   = (const float*)d_in[9];
    const float* rms2   = (const float*)d_in[10];
    float* out = (float*)d_out;

    __half *h, *attn, *gu, *qh, *kh, *vh, *gate, *wqkv, *wo, *wg, *wu, *wd;
    float *q, *k, *x1;
    cudaGetSymbolAddress((void**)&h,    g_h);
    cudaGetSymbolAddress((void**)&q,    g_q);
    cudaGetSymbolAddress((void**)&k,    g_k);
    cudaGetSymbolAddress((void**)&qh,   g_qh);
    cudaGetSymbolAddress((void**)&kh,   g_kh);
    cudaGetSymbolAddress((void**)&vh,   g_vh);
    cudaGetSymbolAddress((void**)&attn, g_attn);
    cudaGetSymbolAddress((void**)&x1,   g_x1);
    cudaGetSymbolAddress((void**)&gate, g_gate);
    cudaGetSymbolAddress((void**)&gu,   g_gu);
    cudaGetSymbolAddress((void**)&wqkv, g_wqkv);
    cudaGetSymbolAddress((void**)&wo,   g_wo);
    cudaGetSymbolAddress((void**)&wg,   g_wg);
    cudaGetSymbolAddress((void**)&wu,   g_wu);
    cudaGetSymbolAddress((void**)&wd,   g_wd);

    cudaFuncSetAttribute(attn16_kernel, cudaFuncAttributeMaxDynamicSharedMemorySize, ATT_SMEM);
    cudaFuncSetAttribute(gemm_f16_kernel<1,0>, cudaFuncAttributeMaxDynamicSharedMemorySize, GEMM_SMEM);
    cudaFuncSetAttribute(gemm_f16_kernel<2,1>, cudaFuncAttributeMaxDynamicSharedMemorySize, GEMM_SMEM);
    cudaFuncSetAttribute(gemm_f16_kernel<3,1>, cudaFuncAttributeMaxDynamicSharedMemorySize, GEMM_SMEM);
    cudaFuncSetAttribute(gemm_f16_kernel<4,0>, cudaFuncAttributeMaxDynamicSharedMemorySize, GEMM_SMEM);

    // 0. ALL weights -> fp16 in ONE launch (block-granular segments, MLP=8)
    f2h_all_kernel<<<(unsigned)F2H_BLOCKS, 256>>>(
        (const float4*)w_q, (const float4*)w_k, (const float4*)w_v,
        (const float4*)w_o, (const float4*)w_gate, (const float4*)w_up,
        (const float4*)w_down,
        (__half2*)wqkv, (__half2*)wo, (__half2*)wg, (__half2*)wu, (__half2*)wd);

    // 1. h = rmsnorm(x) * rms1  (fp16)
    rmsnorm_kernel<<<T_, 256>>>(x, rms1, h);
    // 2. fused QKV projection (q fp32, k fp32, v fp16), N=6144
    gemm_f16_kernel<4,0><<<dim3(48, T_ / 128), 256, GEMM_SMEM>>>(h, wqkv, nullptr, q, k, vh, 0, H_);
    // 3. fused RoPE (fp32 -> fp16), 4 heads per block
    rope2_kernel<<<dim3(T_, (HQ_ + HKV_) / 4), 256>>>(q, k, pos, qh, kh);
    // 4. causal attention (fp16 tensor cores, balanced)
    attn16_kernel<<<dim3(8, HQ_), 256, ATT_SMEM>>>(qh, kh, vh, attn);
    // 5. x1 = x + attn @ w_o^T
    gemm_f16_kernel<1,0><<<dim3(H_ / 128, T_ / 128), 256, GEMM_SMEM>>>(attn, wo, x, x1, nullptr, nullptr, H_, H_);
    // 6. h = rmsnorm(x1) * rms2 (fp16)
    rmsnorm_kernel<<<T_, 256>>>(x1, rms2, h);
    // 7. gate = silu(h @ w_gate^T)  (fp16)
    gemm_f16_kernel<2,1><<<dim3(I_ / 128, T_ / 128), 256, GEMM_SMEM>>>(h, wg, nullptr, gate, nullptr, nullptr, I_, H_);
    // 8. gu = gate * (h @ w_up^T)  (fp16)
    gemm_f16_kernel<3,1><<<dim3(I_ / 128, T_ / 128), 256, GEMM_SMEM>>>(h, wu, gate, gu, nullptr, nullptr, I_, H_);
    // 9. out = x1 + gu @ w_down^T
    gemm_f16_kernel<1,0><<<dim3(H_ / 128, T_ / 128), 256, GEMM_SMEM>>>(gu, wd, x1, out, nullptr, nullptr, H_, I_);
}

// round 17
// speedup vs baseline: 1.6165x; 1.0058x over previous
#include <cuda_runtime.h>
#include <cuda_fp16.h>
#include <cstddef>
#include <cstdint>
#include <math.h>

// ---------------- problem constants ----------------
#define T_  2048
#define H_  4096
#define HQ_ 32
#define HKV_ 8
#define D_  128
#define I_  14336

// ---------------- scratch (device globals; no allocation allowed) ----------------
// LAYOUT FROZEN (order & sizes identical to round 12/14/15/16)
__device__ __half g_h   [T_ * H_];            // rmsnorm out (fp16)
__device__ float  g_q   [T_ * HQ_ * D_];      // q proj fp32 (pre-rope)
__device__ float  g_k   [T_ * HKV_ * D_];     // k proj fp32 (pre-rope)
__device__ __half g_qh  [T_ * HQ_ * D_];      // q fp16 post-rope
__device__ __half g_kh  [T_ * HKV_ * D_];     // k fp16 post-rope
__device__ __half g_vh  [T_ * HKV_ * D_];     // v fp16
__device__ __half g_attn[T_ * H_];            // attention out (fp16)
__device__ float  g_x1  [T_ * H_];
__device__ __half g_gate[T_ * (size_t)I_];
__device__ __half g_gu  [T_ * (size_t)I_];
__device__ __half g_wqkv[(size_t)(H_ + 2 * HKV_ * D_) * H_];
__device__ __half g_wo[(size_t)H_ * H_];
__device__ __half g_wg[(size_t)I_ * H_];
__device__ __half g_wu[(size_t)I_ * H_];
__device__ __half g_wd[(size_t)H_ * I_];

// ---------------- helpers ----------------
__device__ __forceinline__ uint32_t smem_u32(const void* p) {
    return (uint32_t)__cvta_generic_to_shared(p);
}
__device__ __forceinline__ void cp_async16(uint32_t saddr, const void* gmem) {
    asm volatile("cp.async.cg.shared.global [%0], [%1], 16;\n" :: "r"(saddr), "l"(gmem));
}
#define CP_COMMIT() asm volatile("cp.async.commit_group;\n" ::: "memory")

__device__ __forceinline__ void ldsm4(uint32_t& r0, uint32_t& r1, uint32_t& r2,
                                      uint32_t& r3, uint32_t addr) {
    asm volatile("ldmatrix.sync.aligned.m8n8.x4.shared.b16 {%0,%1,%2,%3}, [%4];"
                 : "=r"(r0), "=r"(r1), "=r"(r2), "=r"(r3) : "r"(addr));
}
__device__ __forceinline__ void ldsm4t(uint32_t& r0, uint32_t& r1, uint32_t& r2,
                                       uint32_t& r3, uint32_t addr) {
    asm volatile("ldmatrix.sync.aligned.m8n8.x4.trans.shared.b16 {%0,%1,%2,%3}, [%4];"
                 : "=r"(r0), "=r"(r1), "=r"(r2), "=r"(r3) : "r"(addr));
}
__device__ __forceinline__ void mma_f16(float* c,
    uint32_t a0, uint32_t a1, uint32_t a2, uint32_t a3, uint32_t b0, uint32_t b1)
{
    asm volatile(
        "mma.sync.aligned.m16n8k16.row.col.f32.f16.f16.f32 "
        "{%0,%1,%2,%3}, {%4,%5,%6,%7}, {%8,%9}, {%0,%1,%2,%3};"
        : "+f"(c[0]), "+f"(c[1]), "+f"(c[2]), "+f"(c[3])
        : "r"(a0), "r"(a1), "r"(a2), "r"(a3), "r"(b0), "r"(b1));
}
__device__ __forceinline__ uint32_t packh2(float a, float b) {
    __half2 h = __floats2half2_rn(a, b);
    return *(uint32_t*)&h;
}

// ---------------- fused weight convert fp32 -> fp16 (block-granular, MLP=8) ----------------
#define S_WQ 4194304L
#define S_WK 1048576L
#define S_WV 1048576L
#define S_WO 4194304L
#define S_WG 14680064L
#define S_WU 14680064L
#define S_WD 14680064L
#define S_TOTAL (S_WQ + S_WK + S_WV + S_WO + S_WG + S_WU + S_WD)
#define F2H_BLOCKS (S_TOTAL / 2048)   // 26624, exact

__global__ void __launch_bounds__(256) f2h_all_kernel(
    const float4* __restrict__ wq, const float4* __restrict__ wk,
    const float4* __restrict__ wv, const float4* __restrict__ wo,
    const float4* __restrict__ wg, const float4* __restrict__ wu,
    const float4* __restrict__ wd,
    __half2* __restrict__ dqkv, __half2* __restrict__ dwo,
    __half2* __restrict__ dwg, __half2* __restrict__ dwu,
    __half2* __restrict__ dwd)
{
    long j = (long)blockIdx.x * 2048;   // block-base in float4 units
    const float4* src;
    __half2* dst;
    if (j < S_WQ)                      { src = wq; dst = dqkv; }
    else if ((j -= S_WQ) < S_WK)       { src = wk; dst = dqkv + 2 * S_WQ; }
    else if ((j -= S_WK) < S_WV)       { src = wv; dst = dqkv + 2 * (S_WQ + S_WK); }
    else if ((j -= S_WV) < S_WO)       { src = wo; dst = dwo; }
    else if ((j -= S_WO) < S_WG)       { src = wg; dst = dwg; }
    else if ((j -= S_WG) < S_WU)       { src = wu; dst = dwu; }
    else                { j -= S_WU;     src = wd; dst = dwd; }

    const long base = j + threadIdx.x;
    float4 v[8];
#pragma unroll
    for (int r = 0; r < 8; r++) v[r] = src[base + r * 256];
#pragma unroll
    for (int r = 0; r < 8; r++) {
        const long idx = base + r * 256;
        dst[2 * idx]     = __floats2half2_rn(v[r].x, v[r].y);
        dst[2 * idx + 1] = __floats2half2_rn(v[r].z, v[r].w);
    }
}

// ---------------- RMSNorm (fp16 output) ----------------
__global__ void __launch_bounds__(256) rmsnorm_kernel(
    const float* __restrict__ x, const float* __restrict__ w, __half* __restrict__ out)
{
    const int row = blockIdx.x;
    const float4* xv = (const float4*)(x + (size_t)row * H_);
    const float4* wv = (const float4*)w;
    __half2* ov = (__half2*)(out + (size_t)row * H_);

    float4 buf[4];
    float ss = 0.f;
#pragma unroll
    for (int i = 0; i < 4; i++) {
        float4 v = xv[threadIdx.x + i * 256];
        buf[i] = v;
        ss += v.x * v.x + v.y * v.y + v.z * v.z + v.w * v.w;
    }
#pragma unroll
    for (int o = 16; o; o >>= 1) ss += __shfl_xor_sync(0xffffffffu, ss, o);

    __shared__ float wsum[8];
    __shared__ float s_inv;
    if ((threadIdx.x & 31) == 0) wsum[threadIdx.x >> 5] = ss;
    __syncthreads();
    if (threadIdx.x == 0) {
        float tot = 0.f;
#pragma unroll
        for (int i = 0; i < 8; i++) tot += wsum[i];
        s_inv = rsqrtf(tot * (1.f / (float)H_) + 1e-5f);
    }
    __syncthreads();
    const float inv = s_inv;
#pragma unroll
    for (int i = 0; i < 4; i++) {
        float4 v = buf[i];
        float4 ww = wv[threadIdx.x + i * 256];
        ov[(threadIdx.x + i * 256) * 2]     = __floats2half2_rn(v.x * inv * ww.x, v.y * inv * ww.y);
        ov[(threadIdx.x + i * 256) * 2 + 1] = __floats2half2_rn(v.z * inv * ww.z, v.w * inv * ww.w);
    }
}

// ---------------- fused RoPE (q + k): fp32 in, fp16 out, 4 heads/block ----------------
__global__ void __launch_bounds__(256) rope2_kernel(
    const float* __restrict__ qi, const float* __restrict__ ki,
    const int* __restrict__ pos,
    __half* __restrict__ qo, __half* __restrict__ ko)
{
    const int tt = blockIdx.x;
    int h = blockIdx.y * 4 + (threadIdx.x >> 6);   // 0..39
    const int j = threadIdx.x & 63;
    const float p = (float)pos[tt];
    const float invf = expf(-(float)j * 0.20503692777194262f);
    float s, c;
    sincosf(p * invf, &s, &c);
    const float* base;
    __half* ob;
    if (h < HQ_) {
        base = qi + ((size_t)tt * HQ_ + h) * D_ + j;
        ob   = qo + ((size_t)tt * HQ_ + h) * D_ + j;
    } else {
        h -= HQ_;
        base = ki + ((size_t)tt * HKV_ + h) * D_ + j;
        ob   = ko + ((size_t)tt * HKV_ + h) * D_ + j;
    }
    const float x1v = base[0];
    const float x2v = base[64];
    ob[0]  = __float2half(x1v * c - x2v * s);
    ob[64] = __float2half(x2v * c + x1v * s);
}

// ---------------- fp16 tensor-core GEMM: C[M,N] = A[M,K] * B[N,K]^T ----------------
// ROUND-9 macro-config; fragments double-buffered across ks (load ks+1 during ks MMAs).
// MODE 0: store  1: C=Cin(f32)+acc  2: C=silu(acc)  3: C=Cin(f16)*acc  4: QKV split
// OUTH: 1 -> fp16 output, 0 -> fp32 output
#define STAGE_A 16384
#define STAGE_BYTES 32768
#define GEMM_SMEM (3 * STAGE_BYTES)

template <int MODE, int OUTH>
__global__ void __launch_bounds__(256, 2) gemm_f16_kernel(
    const __half* __restrict__ A, const __half* __restrict__ B,
    const void* __restrict__ Cin, void* __restrict__ Cv,
    void* __restrict__ Cv2, void* __restrict__ Cv3, int N, int K)
{
    extern __shared__ __align__(1024) char smem[];
    const uint32_t sbase = smem_u32(smem);
    const int tid  = threadIdx.x;
    const int wid  = tid >> 5;
    const int lane = tid & 31;
    const int warpM = (wid >> 2) * 64;
    const int warpN = (wid & 3) * 32;
    const size_t arow0 = (size_t)blockIdx.y * 128;
    const size_t brow0 = (size_t)blockIdx.x * 128;
    const int ntiles = K >> 6;

    const int lrow = tid >> 1;
    const int lch  = (tid & 1) * 4;
    const __half* Ag = A + (arow0 + lrow) * K + lch * 8;
    const __half* Bg = B + (brow0 + lrow) * K + lch * 8;
    uint32_t s_off[4];
#pragma unroll
    for (int i = 0; i < 4; i++) {
        uint32_t o = (uint32_t)(lrow * 128 + (lch + i) * 16);
        s_off[i] = o ^ ((o >> 3) & 0x70);
    }

#define LOADT(t, slot)                                                   \
    {                                                                    \
        const uint32_t sa = sbase + (slot) * STAGE_BYTES;                \
        const __half* ag = Ag + (size_t)(t) * 64;                        \
        const __half* bg = Bg + (size_t)(t) * 64;                        \
        _Pragma("unroll")                                                \
        for (int i = 0; i < 4; i++) {                                    \
            cp_async16(sa + s_off[i], ag + i * 8);                       \
            cp_async16(sa + STAGE_A + s_off[i], bg + i * 8);             \
        }                                                                \
    }

    uint32_t aRow[4], aMask[4], bRow[2], bMask[2];
    const int kbA = (lane >> 4) * 16;
    {
        const int r = lane & 15;
#pragma unroll
        for (int mi = 0; mi < 4; mi++) {
            uint32_t o = (uint32_t)((warpM + mi * 16 + r) * 128);
            aRow[mi]  = o;
            aMask[mi] = (o >> 3) & 0x70;
        }
    }
    const int rn  = (lane & 7) + ((lane >> 4) << 3);
    const int kbB = ((lane >> 3) & 1) * 16;
    {
#pragma unroll
        for (int ni = 0; ni < 2; ni++) {
            uint32_t o = (uint32_t)((warpN + ni * 16 + rn) * 128);
            bRow[ni]  = o;
            bMask[ni] = (o >> 3) & 0x70;
        }
    }

    float acc[4][4][4];
#pragma unroll
    for (int mi = 0; mi < 4; mi++)
#pragma unroll
        for (int nj = 0; nj < 4; nj++)
#pragma unroll
            for (int r = 0; r < 4; r++) acc[mi][nj][r] = 0.f;

    LOADT(0, 0); CP_COMMIT();
    LOADT(1, 1); CP_COMMIT();

    // double-buffered fragment registers
    uint32_t afr[2][4][4], bfr[2][2][4];

#define LOAD_FRAGS(buf, ks)                                                          \
    {                                                                                \
        _Pragma("unroll")                                                            \
        for (int ni = 0; ni < 2; ni++)                                               \
            ldsm4(bfr[buf][ni][0], bfr[buf][ni][1], bfr[buf][ni][2], bfr[buf][ni][3],\
                  sa + STAGE_A + bRow[ni] + (((uint32_t)(kbB + (ks) * 32)) ^ bMask[ni])); \
        _Pragma("unroll")                                                            \
        for (int mi = 0; mi < 4; mi++)                                               \
            ldsm4(afr[buf][mi][0], afr[buf][mi][1], afr[buf][mi][2], afr[buf][mi][3],\
                  sa + aRow[mi] + (((uint32_t)(kbA + (ks) * 32)) ^ aMask[mi]));      \
    }

    for (int t = 0; t < ntiles; t++) {
        asm volatile("cp.async.wait_group 1;\n" ::: "memory");
        __syncthreads();
        if (t + 2 < ntiles) { LOADT(t + 2, (t + 2) % 3); }
        CP_COMMIT();

        const uint32_t sa = sbase + (t % 3) * STAGE_BYTES;
        LOAD_FRAGS(0, 0);
#pragma unroll
        for (int ks = 0; ks < 4; ks++) {
            const int cur = ks & 1;
            if (ks < 3) { LOAD_FRAGS(cur ^ 1, ks + 1); }
#pragma unroll
            for (int mi = 0; mi < 4; mi++)
#pragma unroll
                for (int nj = 0; nj < 4; nj++)
                    mma_f16(acc[mi][nj],
                            afr[cur][mi][0], afr[cur][mi][1], afr[cur][mi][2], afr[cur][mi][3],
                            bfr[cur][nj >> 1][(nj & 1) * 2], bfr[cur][nj >> 1][(nj & 1) * 2 + 1]);
        }
    }
#undef LOAD_FRAGS
#undef LOADT

    // epilogue
    const int r0 = (int)arow0 + warpM + (lane >> 2);
    if (MODE == 4) {
        const int gcol0 = blockIdx.x * 128 + warpN + (lane & 3) * 2;
        float* outF = nullptr;
        __half* outH = nullptr;
        int Nout, col0;
        if (gcol0 < 4096)      { outF = (float*)Cv;  Nout = H_;         col0 = gcol0; }
        else if (gcol0 < 5120) { outF = (float*)Cv2; Nout = HKV_ * D_;  col0 = gcol0 - 4096; }
        else                   { outH = (__half*)Cv3; Nout = HKV_ * D_; col0 = gcol0 - 5120; }
#pragma unroll
        for (int mi = 0; mi < 4; mi++) {
#pragma unroll
            for (int h = 0; h < 2; h++) {
                const int row = r0 + mi * 16 + h * 8;
#pragma unroll
                for (int nj = 0; nj < 4; nj++) {
                    const int col = col0 + nj * 8;
                    float vx = acc[mi][nj][h * 2 + 0];
                    float vy = acc[mi][nj][h * 2 + 1];
                    if (outF) {
                        *(float2*)(outF + (size_t)row * Nout + col) = make_float2(vx, vy);
                    } else {
                        *(__half2*)(outH + (size_t)row * Nout + col) = __floats2half2_rn(vx, vy);
                    }
                }
            }
        }
        return;
    }

    const int c0 = blockIdx.x * 128 + warpN + (lane & 3) * 2;
#pragma unroll
    for (int mi = 0; mi < 4; mi++) {
#pragma unroll
        for (int h = 0; h < 2; h++) {
            const int row = r0 + mi * 16 + h * 8;
#pragma unroll
            for (int nj = 0; nj < 4; nj++) {
                const int col = c0 + nj * 8;
                float vx = acc[mi][nj][h * 2 + 0];
                float vy = acc[mi][nj][h * 2 + 1];
                if (MODE == 1) {
                    const float* cin = (const float*)Cin + (size_t)row * N + col;
                    vx += cin[0];
                    vy += cin[1];
                } else if (MODE == 2) {
                    vx = vx / (1.f + expf(-vx));
                    vy = vy / (1.f + expf(-vy));
                } else if (MODE == 3) {
                    const __half2 c2 = *(const __half2*)((const __half*)Cin + (size_t)row * N + col);
                    const float2 cf = __half22float2(c2);
                    vx *= cf.x;
                    vy *= cf.y;
                }
                if (OUTH) {
                    __half2* dst = (__half2*)((__half*)Cv + (size_t)row * N + col);
                    *dst = __floats2half2_rn(vx, vy);
                } else {
                    float2* dst = (float2*)((float*)Cv + (size_t)row * N + col);
                    *dst = make_float2(vx, vy);
                }
            }
        }
    }
}

// ---------------- fp16 tensor-core causal flash attention ----------------
// grid (8, HQ): CTA bx processes q-blocks {bx, 15-bx} -> uniform 32 KV-tiles per CTA.
#define AQ_OFF   0
#define AKV_OFF  32768
#define AKV_STRIDE 32768
#define ATT_SMEM (32768 + 2 * AKV_STRIDE)   // 96KB

__global__ void __launch_bounds__(256) attn16_kernel(
    const __half* __restrict__ qh, const __half* __restrict__ kh,
    const __half* __restrict__ vh, __half* __restrict__ o)
{
    extern __shared__ __align__(1024) char smem[];
    const uint32_t sbase = smem_u32(smem);
    const int tid  = threadIdx.x;
    const int wid  = tid >> 5;
    const int lane = tid & 31;
    const int bx   = blockIdx.x;        // 0..7
    const int head = blockIdx.y;
    const int kvh  = head >> 2;
    const float scale = 0.08838834764831845f;

    const int rA    = lane & 15;
    const int kbA   = (lane >> 4) * 16;
    const int rnB   = (lane & 7) + ((lane >> 4) << 3);
    const int kbB   = ((lane >> 3) & 1) * 16;
    const int rV    = (lane & 7) + ((lane >> 3) & 1) * 8;
    const int dbV   = ((lane >> 4) & 1) * 16;

#define LOADKV(kt, buf)                                                              \
    {                                                                                \
        const int k0l = (kt) * 64;                                                   \
        const uint32_t kb = sbase + AKV_OFF + (buf) * AKV_STRIDE;                    \
        _Pragma("unroll")                                                            \
        for (int i = 0; i < 4; i++) {                                                \
            const int chunk = tid + 256 * i;                                         \
            const int seg = chunk >> 9;                                              \
            const int row = (chunk >> 3) & 63;                                       \
            const int off = chunk & 7;                                               \
            const uint32_t ro = (uint32_t)(row * 128);                               \
            const uint32_t sw = ro + (((uint32_t)(off * 16)) ^ ((ro >> 3) & 0x70));  \
            const size_t gi = (size_t)(k0l + row) * (HKV_ * D_) + kvh * D_           \
                            + seg * 64 + off * 8;                                    \
            cp_async16(kb + seg * 8192 + sw, kh + gi);                               \
            cp_async16(kb + 16384 + seg * 8192 + sw, vh + gi);                       \
        }                                                                            \
    }

#pragma unroll 1
    for (int it = 0; it < 2; it++) {
        const int qblk = (it == 0) ? bx : (15 - bx);
        const int q0   = qblk * 128;
        const int qr0  = q0 + wid * 16;

        // ---- load Q tile ----
#pragma unroll
        for (int i = 0; i < 8; i++) {
            const int chunk = tid + 256 * i;
            const int seg = chunk >> 10;
            const int row = (chunk >> 3) & 127;
            const int off = chunk & 7;
            const uint32_t ro = (uint32_t)(row * 128);
            const uint32_t sw = ro + (((uint32_t)(off * 16)) ^ ((ro >> 3) & 0x70));
            cp_async16(sbase + AQ_OFF + seg * 16384 + sw,
                       qh + (size_t)(q0 + row) * (HQ_ * D_) + head * D_ + seg * 64 + off * 8);
        }
        CP_COMMIT();
        LOADKV(0, 0); CP_COMMIT();

        uint32_t qf[8][4];
        float accO[16][4];
#pragma unroll
        for (int nj = 0; nj < 16; nj++)
#pragma unroll
            for (int r = 0; r < 4; r++) accO[nj][r] = 0.f;
        float m1 = -1e30f, m2 = -1e30f, l1 = 0.f, l2 = 0.f;

        const int ktmax = 2 * qblk + 1;
        for (int kt = 0; kt <= ktmax; kt++) {
            if (kt < ktmax) {
                LOADKV(kt + 1, (kt + 1) & 1);
                CP_COMMIT();
                asm volatile("cp.async.wait_group 1;\n" ::: "memory");
            } else {
                asm volatile("cp.async.wait_group 0;\n" ::: "memory");
            }
            __syncthreads();

            if (kt == 0) {
#pragma unroll
                for (int ks = 0; ks < 8; ks++) {
                    const int seg = ks >> 2;
                    const uint32_t ro = (uint32_t)((wid * 16 + rA) * 128);
                    const uint32_t addr = sbase + AQ_OFF + seg * 16384 + ro
                        + (((uint32_t)(kbA + (ks & 3) * 32)) ^ ((ro >> 3) & 0x70));
                    ldsm4(qf[ks][0], qf[ks][1], qf[ks][2], qf[ks][3], addr);
                }
            }

            const int k0 = kt * 64;
            if (k0 <= qr0 + 15) {
                const uint32_t kbuf = sbase + AKV_OFF + (kt & 1) * AKV_STRIDE;
                float s[8][4];
#pragma unroll
                for (int nj = 0; nj < 8; nj++)
#pragma unroll
                    for (int r = 0; r < 4; r++) s[nj][r] = 0.f;

#pragma unroll
                for (int ks = 0; ks < 8; ks++) {
                    const int seg = ks >> 2;
                    uint32_t b[4][4];
#pragma unroll
                    for (int ni = 0; ni < 4; ni++) {
                        const uint32_t ro = (uint32_t)((ni * 16 + rnB) * 128);
                        ldsm4(b[ni][0], b[ni][1], b[ni][2], b[ni][3],
                              kbuf + seg * 8192 + ro
                              + (((uint32_t)(kbB + (ks & 3) * 32)) ^ ((ro >> 3) & 0x70)));
                    }
#pragma unroll
                    for (int nj = 0; nj < 8; nj++)
                        mma_f16(s[nj], qf[ks][0], qf[ks][1], qf[ks][2], qf[ks][3],
                                b[nj >> 1][(nj & 1) * 2], b[nj >> 1][(nj & 1) * 2 + 1]);
                }

                const int row1 = qr0 + (lane >> 2);
                const int row2 = row1 + 8;
                float rmax1 = -1e30f, rmax2 = -1e30f;
#pragma unroll
                for (int nj = 0; nj < 8; nj++) {
                    const int c0 = k0 + nj * 8 + (lane & 3) * 2;
                    float v0 = s[nj][0] * scale, v1 = s[nj][1] * scale;
                    float v2 = s[nj][2] * scale, v3 = s[nj][3] * scale;
                    if (c0 > row1)     v0 = -1e30f;
                    if (c0 + 1 > row1) v1 = -1e30f;
                    if (c0 > row2)     v2 = -1e30f;
                    if (c0 + 1 > row2) v3 = -1e30f;
                    s[nj][0] = v0; s[nj][1] = v1; s[nj][2] = v2; s[nj][3] = v3;
                    rmax1 = fmaxf(rmax1, fmaxf(v0, v1));
                    rmax2 = fmaxf(rmax2, fmaxf(v2, v3));
                }
#pragma unroll
                for (int off = 1; off <= 2; off <<= 1) {
                    rmax1 = fmaxf(rmax1, __shfl_xor_sync(0xffffffffu, rmax1, off));
                    rmax2 = fmaxf(rmax2, __shfl_xor_sync(0xffffffffu, rmax2, off));
                }
                const float mn1 = fmaxf(m1, rmax1);
                const float mn2 = fmaxf(m2, rmax2);
                const float al1 = expf(m1 - mn1);
                const float al2 = expf(m2 - mn2);
                m1 = mn1; m2 = mn2;

                float ps1 = 0.f, ps2 = 0.f;
#pragma unroll
                for (int nj = 0; nj < 8; nj++) {
                    float p0 = expf(s[nj][0] - mn1);
                    float p1 = expf(s[nj][1] - mn1);
                    float p2 = expf(s[nj][2] - mn2);
                    float p3 = expf(s[nj][3] - mn2);
                    s[nj][0] = p0; s[nj][1] = p1; s[nj][2] = p2; s[nj][3] = p3;
                    ps1 += p0 + p1;
                    ps2 += p2 + p3;
                }
#pragma unroll
                for (int off = 1; off <= 2; off <<= 1) {
                    ps1 += __shfl_xor_sync(0xffffffffu, ps1, off);
                    ps2 += __shfl_xor_sync(0xffffffffu, ps2, off);
                }
                l1 = l1 * al1 + ps1;
                l2 = l2 * al2 + ps2;
#pragma unroll
                for (int nj = 0; nj < 16; nj++) {
                    accO[nj][0] *= al1; accO[nj][1] *= al1;
                    accO[nj][2] *= al2; accO[nj][3] *= al2;
                }

                const uint32_t vbuf = kbuf + 16384;
#pragma unroll
                for (int kv = 0; kv < 4; kv++) {
                    const uint32_t a0 = packh2(s[2 * kv][0],     s[2 * kv][1]);
                    const uint32_t a1 = packh2(s[2 * kv][2],     s[2 * kv][3]);
                    const uint32_t a2 = packh2(s[2 * kv + 1][0], s[2 * kv + 1][1]);
                    const uint32_t a3 = packh2(s[2 * kv + 1][2], s[2 * kv + 1][3]);
#pragma unroll
                    for (int p = 0; p < 8; p++) {
                        const int seg = p >> 2;
                        const uint32_t ro = (uint32_t)((kv * 16 + rV) * 128);
                        uint32_t b0, b1, b2, b3;
                        ldsm4t(b0, b1, b2, b3,
                               vbuf + seg * 8192 + ro
                               + (((uint32_t)((p & 3) * 32 + dbV)) ^ ((ro >> 3) & 0x70)));
                        mma_f16(accO[2 * p],     a0, a1, a2, a3, b0, b1);
                        mma_f16(accO[2 * p + 1], a0, a1, a2, a3, b2, b3);
                    }
                }
            }
            __syncthreads();
        }

        // ---- epilogue for this q-block ----
        const float inv1 = 1.f / l1;
        const float inv2 = 1.f / l2;
        const int row1 = qr0 + (lane >> 2);
        const int colb = head * D_ + (lane & 3) * 2;
#pragma unroll
        for (int nj = 0; nj < 16; nj++) {
            __half2* d1 = (__half2*)(o + (size_t)row1 * H_ + colb + nj * 8);
            __half2* d2 = (__half2*)(o + (size_t)(row1 + 8) * H_ + colb + nj * 8);
            *d1 = __floats2half2_rn(accO[nj][0] * inv1, accO[nj][1] * inv1);
            *d2 = __floats2half2_rn(accO[nj][2] * inv2, accO[nj][3] * inv2);
        }
    }
#undef LOADKV
}

// ---------------- launch ----------------
extern "C" void kernel_launch(void* const* d_in, const int* in_sizes, int n_in,
                              void* d_out, int out_size)
{
    (void)in_sizes; (void)n_in; (void)out_size;
    const float* x      = (const float*)d_in[0];
    const int*   pos    = (const int*)  d_in[1];
    const float* w_q    = (const float*)d_in[2];
    const float* w_k    = (const float*)d_in[3];
    const float* w_v    = (const float*)d_in[4];
    const float* w_o    = (const float*)d_in[5];
    const float* w_gate = (const float*)d_in[6];
    const float* w_up   = (const float*)d_in[7];
    const float* w_down = (const float*)d_in[8];
    const float* rms1   = (const float*)d_in[9];
    const float* rms2   = (const float*)d_in[10];
    float* out = (float*)d_out;

    __half *h, *attn, *gu, *qh, *kh, *vh, *gate, *wqkv, *wo, *wg, *wu, *wd;
    float *q, *k, *x1;
    cudaGetSymbolAddress((void**)&h,    g_h);
    cudaGetSymbolAddress((void**)&q,    g_q);
    cudaGetSymbolAddress((void**)&k,    g_k);
    cudaGetSymbolAddress((void**)&qh,   g_qh);
    cudaGetSymbolAddress((void**)&kh,   g_kh);
    cudaGetSymbolAddress((void**)&vh,   g_vh);
    cudaGetSymbolAddress((void**)&attn, g_attn);
    cudaGetSymbolAddress((void**)&x1,   g_x1);
    cudaGetSymbolAddress((void**)&gate, g_gate);
    cudaGetSymbolAddress((void**)&gu,   g_gu);
    cudaGetSymbolAddress((void**)&wqkv, g_wqkv);
    cudaGetSymbolAddress((void**)&wo,   g_wo);
    cudaGetSymbolAddress((void**)&wg,   g_wg);
    cudaGetSymbolAddress((void**)&wu,   g_wu);
    cudaGetSymbolAddress((void**)&wd,   g_wd);

    cudaFuncSetAttribute(attn16_kernel, cudaFuncAttributeMaxDynamicSharedMemorySize, ATT_SMEM);
    cudaFuncSetAttribute(gemm_f16_kernel<1,0>, cudaFuncAttributeMaxDynamicSharedMemorySize, GEMM_SMEM);
    cudaFuncSetAttribute(gemm_f16_kernel<2,1>, cudaFuncAttributeMaxDynamicSharedMemorySize, GEMM_SMEM);
    cudaFuncSetAttribute(gemm_f16_kernel<3,1>, cudaFuncAttributeMaxDynamicSharedMemorySize, GEMM_SMEM);
    cudaFuncSetAttribute(gemm_f16_kernel<4,0>, cudaFuncAttributeMaxDynamicSharedMemorySize, GEMM_SMEM);

    // 0. ALL weights -> fp16 in ONE launch (block-granular segments, MLP=8)
    f2h_all_kernel<<<(unsigned)F2H_BLOCKS, 256>>>(
        (const float4*)w_q, (const float4*)w_k, (const float4*)w_v,
        (const float4*)w_o, (const float4*)w_gate, (const float4*)w_up,
        (const float4*)w_down,
        (__half2*)wqkv, (__half2*)wo, (__half2*)wg, (__half2*)wu, (__half2*)wd);

    // 1. h = rmsnorm(x) * rms1  (fp16)
    rmsnorm_kernel<<<T_, 256>>>(x, rms1, h);
    // 2. fused QKV projection (q fp32, k fp32, v fp16), N=6144
    gemm_f16_kernel<4,0><<<dim3(48, T_ / 128), 256, GEMM_SMEM>>>(h, wqkv, nullptr, q, k, vh, 0, H_);
    // 3. fused RoPE (fp32 -> fp16), 4 heads per block
    rope2_kernel<<<dim3(T_, (HQ_ + HKV_) / 4), 256>>>(q, k, pos, qh, kh);
    // 4. causal attention (fp16 tensor cores, balanced)
    attn16_kernel<<<dim3(8, HQ_), 256, ATT_SMEM>>>(qh, kh, vh, attn);
    // 5. x1 = x + attn @ w_o^T
    gemm_f16_kernel<1,0><<<dim3(H_ / 128, T_ / 128), 256, GEMM_SMEM>>>(attn, wo, x, x1, nullptr, nullptr, H_, H_);
    // 6. h = rmsnorm(x1) * rms2 (fp16)
    rmsnorm_kernel<<<T_, 256>>>(x1, rms2, h);
    // 7. gate = silu(h @ w_gate^T)  (fp16)
    gemm_f16_kernel<2,1><<<dim3(I_ / 128, T_ / 128), 256, GEMM_SMEM>>>(h, wg, nullptr, gate, nullptr, nullptr, I_, H_);
    // 8. gu = gate * (h @ w_up^T)  (fp16)
    gemm_f16_kernel<3,1><<<dim3(I_ / 128, T_ / 128), 256, GEMM_SMEM>>>(h, wu, gate, gu, nullptr, nullptr, I_, H_);
    // 9. out = x1 + gu @ w_down^T
    gemm_f16_kernel<1,0><<<dim3(H_ / 128, T_ / 128), 256, GEMM_SMEM>>>(gu, wd, x1, out, nullptr, nullptr, H_, I_);
}